// round 1
// baseline (speedup 1.0000x reference)
#include <cuda_runtime.h>
#include <cstdint>

#define NB 2048
#define NWORDS (NB / 64)   // 32

// ---------------- device scratch (no allocations allowed) ----------------
__device__ float              g_bnms[NB * 5];          // offset boxes (original order)
__device__ int                g_order[NB];             // sorted pos -> original index
__device__ float              g_pbox[NB * 16];         // per sorted box: x0..3,y0..3,cx,cy,c,s,we,he,area,rad
__device__ unsigned long long g_mask[NB * NWORDS];     // suppression bitmask (sorted order)

// exact (non-contracted) fp32 helpers — must replicate jax/XLA's unfused fp32 ops
__device__ __forceinline__ float xmul(float a, float b) { return __fmul_rn(a, b); }
__device__ __forceinline__ float xadd(float a, float b) { return __fadd_rn(a, b); }
__device__ __forceinline__ float xsub(float a, float b) { return __fsub_rn(a, b); }
__device__ __forceinline__ float xdiv(float a, float b) { return __fdiv_rn(a, b); }
__device__ __forceinline__ float xcross(float ax, float ay, float bx, float by) {
    return xsub(xmul(ax, by), xmul(ay, bx));
}

// ---------------- kernel A: reductions + offsets + sort + precompute ----------------
__global__ void __launch_bounds__(1024) prep_sort_kernel(const float* __restrict__ boxes,
                                                         const float* __restrict__ scores,
                                                         const int*   __restrict__ labels) {
    __shared__ float red[1024];
    __shared__ unsigned long long keys[NB];
    __shared__ float s_scale;
    const int tid = threadIdx.x;

    // max over sqrt(w*w+h*h) and max over (cx, cy) — replicate ref fp32 ops
    float m1 = -1e30f, m2 = -1e30f;
    for (int i = tid; i < NB; i += 1024) {
        float cx = boxes[i * 5 + 0], cy = boxes[i * 5 + 1];
        float w  = boxes[i * 5 + 2], h  = boxes[i * 5 + 3];
        float s  = __fsqrt_rn(xadd(xmul(w, w), xmul(h, h)));
        m1 = fmaxf(m1, s);
        m2 = fmaxf(m2, fmaxf(cx, cy));
    }
    red[tid] = m1; __syncthreads();
    for (int s = 512; s > 0; s >>= 1) { if (tid < s) red[tid] = fmaxf(red[tid], red[tid + s]); __syncthreads(); }
    float maxs = red[0]; __syncthreads();
    red[tid] = m2; __syncthreads();
    for (int s = 512; s > 0; s >>= 1) { if (tid < s) red[tid] = fmaxf(red[tid], red[tid + s]); __syncthreads(); }
    float maxc = red[0]; __syncthreads();

    if (tid == 0) {
        float max_radius = xmul(maxs, 0.5f);
        float t = xadd(maxc, max_radius);
        s_scale = xadd(xmul(t, 2.0f), 1.0f);   // (max_coord + max_radius)*2 + 1
    }
    __syncthreads();
    const float scale = s_scale;

    // offset boxes + sort keys (descending score, stable by index -> ascending key)
    for (int i = tid; i < NB; i += 1024) {
        float off = xmul((float)labels[i], scale);
        g_bnms[i * 5 + 0] = xadd(boxes[i * 5 + 0], off);
        g_bnms[i * 5 + 1] = xadd(boxes[i * 5 + 1], off);
        g_bnms[i * 5 + 2] = boxes[i * 5 + 2];
        g_bnms[i * 5 + 3] = boxes[i * 5 + 3];
        g_bnms[i * 5 + 4] = boxes[i * 5 + 4];
        unsigned int sb = __float_as_uint(scores[i]);    // scores >= 0 -> monotone bits
        keys[i] = ((unsigned long long)(sb ^ 0xFFFFFFFFu) << 32) | (unsigned int)i;
    }
    __syncthreads();

    // bitonic sort (ascending key == descending score, index tiebreak)
    for (int k = 2; k <= NB; k <<= 1) {
        for (int j = k >> 1; j > 0; j >>= 1) {
            for (int base = 0; base < NB; base += 1024) {
                int idx = base + tid;
                int ixj = idx ^ j;
                if (ixj > idx) {
                    unsigned long long a = keys[idx], b = keys[ixj];
                    bool up = ((idx & k) == 0);
                    if ((a > b) == up) { keys[idx] = b; keys[ixj] = a; }
                }
            }
            __syncthreads();
        }
    }

    // per sorted box precompute (corners, cos/sin, in-box thresholds, area, circle radius)
    for (int pos = tid; pos < NB; pos += 1024) {
        int orig = (int)(keys[pos] & 0xFFFFFFFFu);
        g_order[pos] = orig;
        float cx = g_bnms[orig * 5 + 0], cy = g_bnms[orig * 5 + 1];
        float w  = g_bnms[orig * 5 + 2], h  = g_bnms[orig * 5 + 3];
        float a  = g_bnms[orig * 5 + 4];
        float c  = (float)cos((double)a);   // correctly-rounded fp32 trig
        float s  = (float)sin((double)a);
        float wh = xmul(w, 0.5f);           // exact
        float hh = xmul(h, 0.5f);
        float* P = &g_pbox[pos * 16];
#pragma unroll
        for (int q = 0; q < 4; q++) {
            float dx = (q == 1 || q == 2) ? wh : -wh;
            float dy = (q >= 2) ? hh : -hh;
            // ref: x = (cx + c*dx) - s*dy ;  y = (cy + s*dx) + c*dy
            P[q]     = xsub(xadd(cx, xmul(c, dx)), xmul(s, dy));
            P[4 + q] = xadd(xadd(cy, xmul(s, dx)), xmul(c, dy));
        }
        P[8]  = cx;  P[9]  = cy;  P[10] = c;  P[11] = s;
        P[12] = xadd(wh, 1e-5f);       // w*0.5 + eps
        P[13] = xadd(hh, 1e-5f);
        P[14] = xmul(w, h);            // area
        P[15] = 0.5f * __fsqrt_rn(w * w + h * h) + 1e-2f;   // conservative circle radius (ours only)
    }
}

// ---------------- exact-replica pairwise intersection area ----------------
__device__ bool pib(float x, float y, const float* __restrict__ B) {
    float px = xsub(x, B[8]);
    float py = xsub(y, B[9]);
    float lx = xadd(xmul(B[10], px), xmul(B[11], py));         //  c*px + s*py
    float ly = xadd(xmul(-B[11], px), xmul(B[10], py));        // -s*px + c*py
    return (fabsf(lx) <= B[12]) && (fabsf(ly) <= B[13]);
}

__device__ float pair_inter_area(const float* __restrict__ A, const float* __restrict__ B) {
    float ptx[24], pty[24];
    bool  mk[24];
#pragma unroll
    for (int q = 0; q < 4; q++) { ptx[q] = A[q]; pty[q] = A[4 + q]; mk[q] = pib(A[q], A[4 + q], B); }
#pragma unroll
    for (int q = 0; q < 4; q++) { ptx[4 + q] = B[q]; pty[4 + q] = B[4 + q]; mk[4 + q] = pib(B[q], B[4 + q], A); }

#pragma unroll
    for (int ea = 0; ea < 4; ea++) {
        float pxx = A[ea], pyy = A[4 + ea];
        float rx = xsub(A[(ea + 1) & 3], pxx), ry = xsub(A[4 + ((ea + 1) & 3)], pyy);
#pragma unroll
        for (int eb = 0; eb < 4; eb++) {
            float qx = B[eb], qy = B[4 + eb];
            float sx = xsub(B[(eb + 1) & 3], qx), sy = xsub(B[4 + ((eb + 1) & 3)], qy);
            float den = xcross(rx, ry, sx, sy);
            float qpx = xsub(qx, pxx), qpy = xsub(qy, pyy);
            bool  dok = fabsf(den) > 1e-9f;
            float tt  = xdiv(xcross(qpx, qpy, sx, sy), den);
            float uu  = xdiv(xcross(qpx, qpy, rx, ry), den);
            bool  v   = dok && (tt >= 0.0f) && (tt <= 1.0f) && (uu >= 0.0f) && (uu <= 1.0f);
            int id = 8 + ea * 4 + eb;
            ptx[id] = xadd(pxx, xmul(tt, rx));
            pty[id] = xadd(pyy, xmul(tt, ry));
            mk[id]  = v;
        }
    }

    int k = 0; float sxm = 0.0f, sym = 0.0f;
    for (int q = 0; q < 24; q++)
        if (mk[q]) { k++; sxm = xadd(sxm, ptx[q]); sym = xadd(sym, pty[q]); }
    if (k < 3) return 0.0f;

    float kk  = (float)k;
    float cxm = xdiv(sxm, kk), cym = xdiv(sym, kk);

    float dxr[24], dyr[24], ang[24];
    for (int q = 0; q < 24; q++) {
        if (mk[q]) {
            dxr[q] = xsub(ptx[q], cxm);
            dyr[q] = xsub(pty[q], cym);
            ang[q] = atan2f(dyr[q], dxr[q]);
        } else {
            ang[q] = 1e9f;
        }
    }

    // stable insertion sort by angle (matches stable argsort; masked 1e9 go last)
    int ord[24];
    for (int q = 0; q < 24; q++) ord[q] = q;
    for (int q = 1; q < 24; q++) {
        int oq = ord[q]; float aq = ang[oq]; int r = q - 1;
        while (r >= 0 && ang[ord[r]] > aq) { ord[r + 1] = ord[r]; r--; }
        ord[r + 1] = oq;
    }

    float tot = 0.0f;
    for (int q = 0; q < k; q++) {
        int nq = (q + 1 < k) ? q + 1 : 0;
        int a0 = ord[q], a1 = ord[nq];
        float cr = xcross(dxr[a0], dyr[a0], dxr[a1], dyr[a1]);
        tot = xadd(tot, cr);
    }
    return xmul(0.5f, fabsf(tot));
}

// ---------------- kernel B: suppression bitmask ----------------
__global__ void __launch_bounds__(64) mask_kernel(const float* __restrict__ thrp) {
    const int by = blockIdx.y, bx = blockIdx.x;
    const int t = threadIdx.x;
    const int i = by * 64 + t;
    if (bx < by) { g_mask[i * NWORDS + bx] = 0ULL; return; }

    __shared__ float sB[64 * 16];
    for (int q = t; q < 64 * 16; q += 64) sB[q] = g_pbox[(bx * 64) * 16 + q];
    __syncthreads();

    float A[16];
#pragma unroll
    for (int q = 0; q < 16; q++) A[q] = g_pbox[i * 16 + q];
    const float thr = thrp[0];

    unsigned long long bits = 0ULL;
    for (int j = 0; j < 64; j++) {
        int col = bx * 64 + j;
        if (col <= i) continue;
        const float* B = &sB[j * 16];
        float dx = A[8] - B[8], dy = A[9] - B[9];
        float rr = A[15] + B[15];
        if (dx * dx + dy * dy > rr * rr) continue;   // disjoint circles -> inter == 0 exactly
        float inter = pair_inter_area(A, B);
        float iou = xdiv(inter, xadd(xsub(xadd(A[14], B[14]), inter), 1e-9f));
        if (iou > thr) bits |= (1ULL << j);
    }
    g_mask[i * NWORDS + bx] = bits;
}

// ---------------- kernel C: greedy scan + output ----------------
__global__ void __launch_bounds__(32) scan_kernel(const float* __restrict__ scores,
                                                  float* __restrict__ out) {
    const int lane = threadIdx.x;   // 0..31, one word per lane
    unsigned long long rem = 0ULL;
    __shared__ unsigned char keep[NB];

    for (int i = 0; i < NB; i++) {
        unsigned long long m = g_mask[i * NWORDS + lane];  // independent of rem -> pipelines
        int owner = i >> 6;
        int alive = (int)((rem >> (i & 63)) & 1ULL) ^ 1;   // valid on owner lane
        alive = __shfl_sync(0xFFFFFFFFu, alive, owner);
        if (alive) rem |= m;
        if (lane == 0) keep[i] = (unsigned char)alive;
    }
    __syncwarp();
    for (int i = lane; i < NB; i += 32) {
        int orig = g_order[i];
        out[orig] = keep[i] ? scores[orig] : 0.0f;
    }
}

// ---------------- launch ----------------
extern "C" void kernel_launch(void* const* d_in, const int* in_sizes, int n_in,
                              void* d_out, int out_size) {
    (void)in_sizes; (void)n_in; (void)out_size;
    const float* boxes  = (const float*)d_in[0];
    const float* scores = (const float*)d_in[1];
    const int*   labels = (const int*)d_in[2];
    const float* thr    = (const float*)d_in[3];
    float* out = (float*)d_out;

    prep_sort_kernel<<<1, 1024>>>(boxes, scores, labels);
    mask_kernel<<<dim3(NWORDS, NWORDS), 64>>>(thr);
    scan_kernel<<<1, 32>>>(scores, out);
}

// round 2
// speedup vs baseline: 1.6049x; 1.6049x over previous
#include <cuda_runtime.h>
#include <cstdint>

#define NB 2048
#define NWORDS (NB / 64)          // 32
#define MAXPAIRS (NB * (NB - 1) / 2 + 64)

typedef unsigned long long u64;
typedef unsigned int u32;

// ---------------- device scratch ----------------
__device__ float g_scale;
__device__ u64   g_keys[NB];
__device__ int   g_order[NB];              // sorted pos -> original index
__device__ float g_pboxs[NB * 16];         // SORTED order: x0..3,y0..3,cx,cy,c,s,we,he,area,rad
__device__ u64   g_mask[NB * NWORDS];      // suppression bitmask (sorted order)
__device__ int   g_paircnt;
__device__ u32   g_pairs[MAXPAIRS];        // packed (i<<11)|j, i<j, sorted indices

// exact (non-contracted) fp32 helpers — replicate jax/XLA unfused fp32 ops
__device__ __forceinline__ float xmul(float a, float b) { return __fmul_rn(a, b); }
__device__ __forceinline__ float xadd(float a, float b) { return __fadd_rn(a, b); }
__device__ __forceinline__ float xsub(float a, float b) { return __fsub_rn(a, b); }
__device__ __forceinline__ float xdiv(float a, float b) { return __fdiv_rn(a, b); }
__device__ __forceinline__ float xcross(float ax, float ay, float bx, float by) {
    return xsub(xmul(ax, by), xmul(ay, bx));
}

// ---------------- kernel A1: reductions + keys (1 block) ----------------
__global__ void __launch_bounds__(1024) reduce_keys_kernel(const float* __restrict__ boxes,
                                                           const float* __restrict__ scores) {
    __shared__ float red[1024];
    const int tid = threadIdx.x;

    float m1 = -1e30f, m2 = -1e30f;
    for (int i = tid; i < NB; i += 1024) {
        float cx = boxes[i * 5 + 0], cy = boxes[i * 5 + 1];
        float w  = boxes[i * 5 + 2], h  = boxes[i * 5 + 3];
        float s  = __fsqrt_rn(xadd(xmul(w, w), xmul(h, h)));
        m1 = fmaxf(m1, s);
        m2 = fmaxf(m2, fmaxf(cx, cy));
    }
    red[tid] = m1; __syncthreads();
    for (int s = 512; s > 0; s >>= 1) { if (tid < s) red[tid] = fmaxf(red[tid], red[tid + s]); __syncthreads(); }
    float maxs = red[0]; __syncthreads();
    red[tid] = m2; __syncthreads();
    for (int s = 512; s > 0; s >>= 1) { if (tid < s) red[tid] = fmaxf(red[tid], red[tid + s]); __syncthreads(); }
    float maxc = red[0];

    if (tid == 0) {
        float max_radius = xmul(maxs, 0.5f);
        float t = xadd(maxc, max_radius);
        g_scale = xadd(xmul(t, 2.0f), 1.0f);   // (max_coord + max_radius)*2 + 1
        g_paircnt = 0;
    }
    for (int i = tid; i < NB; i += 1024) {
        unsigned int sb = __float_as_uint(scores[i]);  // scores >= 0 -> monotone bits
        g_keys[i] = ((u64)(sb ^ 0xFFFFFFFFu) << 32) | (u32)i;
    }
}

// ---------------- kernel A2: rank + precompute into sorted slot ----------------
__global__ void __launch_bounds__(128) rank_prep_kernel(const float* __restrict__ boxes,
                                                        const int*   __restrict__ labels) {
    __shared__ u64 skeys[NB];
    const int tid = threadIdx.x;
    for (int q = tid; q < NB; q += 128) skeys[q] = g_keys[q];
    __syncthreads();

    const int i = blockIdx.x * 128 + tid;    // original index
    const u64 mykey = skeys[i];

    int rank = 0;
#pragma unroll 8
    for (int q = 0; q < NB; q++) rank += (skeys[q] < mykey);

    const float scale = g_scale;
    float off = xmul((float)labels[i], scale);
    float cx = xadd(boxes[i * 5 + 0], off);
    float cy = xadd(boxes[i * 5 + 1], off);
    float w  = boxes[i * 5 + 2];
    float h  = boxes[i * 5 + 3];
    float a  = boxes[i * 5 + 4];
    float c  = (float)cos((double)a);        // correctly-rounded fp32 trig
    float s  = (float)sin((double)a);
    float wh = xmul(w, 0.5f);
    float hh = xmul(h, 0.5f);

    float* P = &g_pboxs[rank * 16];
#pragma unroll
    for (int q = 0; q < 4; q++) {
        float dx = (q == 1 || q == 2) ? wh : -wh;
        float dy = (q >= 2) ? hh : -hh;
        // ref: x = (cx + c*dx) - s*dy ;  y = (cy + s*dx) + c*dy
        P[q]     = xsub(xadd(cx, xmul(c, dx)), xmul(s, dy));
        P[4 + q] = xadd(xadd(cy, xmul(s, dx)), xmul(c, dy));
    }
    P[8]  = cx;  P[9]  = cy;  P[10] = c;  P[11] = s;
    P[12] = xadd(wh, 1e-5f);
    P[13] = xadd(hh, 1e-5f);
    P[14] = xmul(w, h);
    P[15] = 0.5f * __fsqrt_rn(w * w + h * h) + 1e-2f;   // conservative circle radius
    g_order[rank] = i;
}

// ---------------- kernel B1: circle filter -> pair list, zero mask ----------------
__global__ void __launch_bounds__(64) pair_filter_kernel() {
    const int by = blockIdx.y, bx = blockIdx.x;
    if (bx < by) return;                      // those mask words are never written; stay 0
    const int t = threadIdx.x;
    const int i = by * 64 + t;

    g_mask[i * NWORDS + bx] = 0ULL;

    __shared__ float scx[64], scy[64], srad[64];
    int col0 = bx * 64 + t;
    scx[t]  = g_pboxs[col0 * 16 + 8];
    scy[t]  = g_pboxs[col0 * 16 + 9];
    srad[t] = g_pboxs[col0 * 16 + 15];
    __syncthreads();

    const float acx = g_pboxs[i * 16 + 8];
    const float acy = g_pboxs[i * 16 + 9];
    const float ard = g_pboxs[i * 16 + 15];

    for (int j = 0; j < 64; j++) {
        int col = bx * 64 + j;
        if (col <= i) continue;
        float dx = acx - scx[j], dy = acy - scy[j];
        float rr = ard + srad[j];
        if (dx * dx + dy * dy > rr * rr) continue;   // disjoint -> inter == 0 exactly
        int idx = atomicAdd(&g_paircnt, 1);
        if (idx < MAXPAIRS) g_pairs[idx] = ((u32)i << 11) | (u32)col;
    }
}

// ---------------- exact-replica pairwise intersection area ----------------
__device__ __forceinline__ bool pib(float x, float y, const float* __restrict__ B) {
    float px = xsub(x, B[8]);
    float py = xsub(y, B[9]);
    float lx = xadd(xmul(B[10], px), xmul(B[11], py));     //  c*px + s*py
    float ly = xadd(xmul(-B[11], px), xmul(B[10], py));    // -s*px + c*py
    return (fabsf(lx) <= B[12]) && (fabsf(ly) <= B[13]);
}

__device__ float pair_inter_area(const float* __restrict__ A, const float* __restrict__ B) {
    float ptx[24], pty[24];
    bool  mk[24];
#pragma unroll
    for (int q = 0; q < 4; q++) { ptx[q] = A[q]; pty[q] = A[4 + q]; mk[q] = pib(A[q], A[4 + q], B); }
#pragma unroll
    for (int q = 0; q < 4; q++) { ptx[4 + q] = B[q]; pty[4 + q] = B[4 + q]; mk[4 + q] = pib(B[q], B[4 + q], A); }

#pragma unroll
    for (int ea = 0; ea < 4; ea++) {
        float pxx = A[ea], pyy = A[4 + ea];
        float rx = xsub(A[(ea + 1) & 3], pxx), ry = xsub(A[4 + ((ea + 1) & 3)], pyy);
#pragma unroll
        for (int eb = 0; eb < 4; eb++) {
            float qx = B[eb], qy = B[4 + eb];
            float sx = xsub(B[(eb + 1) & 3], qx), sy = xsub(B[4 + ((eb + 1) & 3)], qy);
            float den = xcross(rx, ry, sx, sy);
            float qpx = xsub(qx, pxx), qpy = xsub(qy, pyy);
            bool  dok = fabsf(den) > 1e-9f;
            float tt  = xdiv(xcross(qpx, qpy, sx, sy), den);
            float uu  = xdiv(xcross(qpx, qpy, rx, ry), den);
            bool  v   = dok && (tt >= 0.0f) && (tt <= 1.0f) && (uu >= 0.0f) && (uu <= 1.0f);
            int id = 8 + ea * 4 + eb;
            ptx[id] = xadd(pxx, xmul(tt, rx));
            pty[id] = xadd(pyy, xmul(tt, ry));
            mk[id]  = v;
        }
    }

    int k = 0; float sxm = 0.0f, sym = 0.0f;
    for (int q = 0; q < 24; q++)
        if (mk[q]) { k++; sxm = xadd(sxm, ptx[q]); sym = xadd(sym, pty[q]); }
    if (k < 3) return 0.0f;

    float kk  = (float)k;
    float cxm = xdiv(sxm, kk), cym = xdiv(sym, kk);

    float dxr[24], dyr[24], ang[24];
    for (int q = 0; q < 24; q++) {
        if (mk[q]) {
            dxr[q] = xsub(ptx[q], cxm);
            dyr[q] = xsub(pty[q], cym);
            ang[q] = atan2f(dyr[q], dxr[q]);
        } else {
            ang[q] = 1e9f;
        }
    }

    int ord[24];
    for (int q = 0; q < 24; q++) ord[q] = q;
    for (int q = 1; q < 24; q++) {          // stable insertion sort by angle
        int oq = ord[q]; float aq = ang[oq]; int r = q - 1;
        while (r >= 0 && ang[ord[r]] > aq) { ord[r + 1] = ord[r]; r--; }
        ord[r + 1] = oq;
    }

    float tot = 0.0f;
    for (int q = 0; q < k; q++) {
        int nq = (q + 1 < k) ? q + 1 : 0;
        int a0 = ord[q], a1 = ord[nq];
        tot = xadd(tot, xcross(dxr[a0], dyr[a0], dxr[a1], dyr[a1]));
    }
    return xmul(0.5f, fabsf(tot));
}

// ---------------- kernel B2: one expensive pair per thread ----------------
__global__ void __launch_bounds__(128) pair_iou_kernel(const float* __restrict__ thrp) {
    const int cnt = g_paircnt;
    const float thr = thrp[0];
    const int stride = gridDim.x * blockDim.x;

    for (int idx = blockIdx.x * blockDim.x + threadIdx.x; idx < cnt; idx += stride) {
        u32 p = g_pairs[idx];
        int i = (int)(p >> 11), j = (int)(p & 0x7FFu);

        float A[16], B[16];
        const float4* Ap = (const float4*)&g_pboxs[i * 16];
        const float4* Bp = (const float4*)&g_pboxs[j * 16];
#pragma unroll
        for (int q = 0; q < 4; q++) {
            float4 va = Ap[q], vb = Bp[q];
            A[q*4+0]=va.x; A[q*4+1]=va.y; A[q*4+2]=va.z; A[q*4+3]=va.w;
            B[q*4+0]=vb.x; B[q*4+1]=vb.y; B[q*4+2]=vb.z; B[q*4+3]=vb.w;
        }
        float inter = pair_inter_area(A, B);
        float iou = xdiv(inter, xadd(xsub(xadd(A[14], B[14]), inter), 1e-9f));
        if (iou > thr)
            atomicOr(&g_mask[i * NWORDS + (j >> 6)], 1ULL << (j & 63));
    }
}

// ---------------- kernel C: chunked greedy scan + output ----------------
__device__ __forceinline__ void cp16(u32 smem_dst, const void* gsrc) {
    asm volatile("cp.async.cg.shared.global [%0], [%1], 16;" :: "r"(smem_dst), "l"(gsrc) : "memory");
}
__device__ __forceinline__ void cp_commit() { asm volatile("cp.async.commit_group;" ::: "memory"); }

__global__ void __launch_bounds__(32) scan_kernel(const float* __restrict__ scores,
                                                  float* __restrict__ out) {
    __shared__ u64 sbuf[2][NB];       // 2 x 16KB: one chunk = 64 rows x 32 words
    __shared__ u64 s_keep[NWORDS];
    const int lane = threadIdx.x;
    u64 rem = 0ULL;

    u32 sb0 = (u32)__cvta_generic_to_shared(&sbuf[0][0]);
    u32 sb1 = (u32)__cvta_generic_to_shared(&sbuf[1][0]);

    // preload chunk 0 (16KB contiguous in g_mask)
    {
        const char* src = (const char*)&g_mask[0];
        for (int t = lane; t < 1024; t += 32) cp16(sb0 + t * 16, src + t * 16);
        cp_commit();
    }

    for (int c = 0; c < NWORDS; c++) {
        if (c + 1 < NWORDS) {
            u32 dst = ((c + 1) & 1) ? sb1 : sb0;
            const char* src = (const char*)&g_mask[(c + 1) * 64 * NWORDS];
            for (int t = lane; t < 1024; t += 32) cp16(dst + t * 16, src + t * 16);
            cp_commit();
            asm volatile("cp.async.wait_group 1;" ::: "memory");
        } else {
            asm volatile("cp.async.wait_group 0;" ::: "memory");
        }
        __syncwarp();

        const u64* S = sbuf[c & 1];
        // serial intra-chunk resolve on word c (all lanes redundantly)
        u64 cur = __shfl_sync(0xFFFFFFFFu, rem, c);
        u64 A = 0ULL;
#pragma unroll 4
        for (int j = 0; j < 64; j++) {
            u64 w = S[j * NWORDS + c];
            if (!((cur >> j) & 1ULL)) { cur |= w; A |= 1ULL << j; }
        }
        // parallel rem update across all 32 words
#pragma unroll 4
        for (int j = 0; j < 64; j++)
            if ((A >> j) & 1ULL) rem |= S[j * NWORDS + lane];

        if (lane == 0) s_keep[c] = A;
        __syncwarp();
    }

    for (int i = lane; i < NB; i += 32) {
        int keep = (int)((s_keep[i >> 6] >> (i & 63)) & 1ULL);
        int orig = g_order[i];
        out[orig] = keep ? scores[orig] : 0.0f;
    }
}

// ---------------- launch ----------------
extern "C" void kernel_launch(void* const* d_in, const int* in_sizes, int n_in,
                              void* d_out, int out_size) {
    (void)in_sizes; (void)n_in; (void)out_size;
    const float* boxes  = (const float*)d_in[0];
    const float* scores = (const float*)d_in[1];
    const int*   labels = (const int*)d_in[2];
    const float* thr    = (const float*)d_in[3];
    float* out = (float*)d_out;

    reduce_keys_kernel<<<1, 1024>>>(boxes, scores);
    rank_prep_kernel<<<NB / 128, 128>>>(boxes, labels);
    pair_filter_kernel<<<dim3(NWORDS, NWORDS), 64>>>();
    pair_iou_kernel<<<148, 128>>>(thr);
    scan_kernel<<<1, 32>>>(scores, out);
}

// round 3
// speedup vs baseline: 3.1859x; 1.9851x over previous
#include <cuda_runtime.h>
#include <cstdint>

#define NB 2048
#define NWORDS (NB / 64)          // 32
#define MAXPAIRS (NB * (NB - 1) / 2 + 64)

typedef unsigned long long u64;
typedef unsigned int u32;

// ---------------- device scratch ----------------
__device__ float g_scale;
__device__ u64   g_keys[NB];
__device__ int   g_order[NB];              // sorted pos -> original index
__device__ float g_pboxs[NB * 16];         // SORTED: x0..3,y0..3,cx,cy,c,s,we,he,area,rad
__device__ u64   g_mask[NB * NWORDS];      // suppression bitmask (sorted order)
__device__ u64   g_rownz[NWORDS];          // bit j of word c -> row c*64+j has any suppression
__device__ int   g_paircnt;
__device__ u32   g_pairs[MAXPAIRS];        // packed (i<<11)|j, i<j, sorted indices

// exact (non-contracted) fp32 helpers — replicate jax/XLA unfused fp32 ops
__device__ __forceinline__ float xmul(float a, float b) { return __fmul_rn(a, b); }
__device__ __forceinline__ float xadd(float a, float b) { return __fadd_rn(a, b); }
__device__ __forceinline__ float xsub(float a, float b) { return __fsub_rn(a, b); }
__device__ __forceinline__ float xdiv(float a, float b) { return __fdiv_rn(a, b); }
__device__ __forceinline__ float xcross(float ax, float ay, float bx, float by) {
    return xsub(xmul(ax, by), xmul(ay, bx));
}

// ---------------- kernel A1: reductions + keys (1 block) ----------------
__global__ void __launch_bounds__(1024) reduce_keys_kernel(const float* __restrict__ boxes,
                                                           const float* __restrict__ scores) {
    __shared__ float red[1024];
    const int tid = threadIdx.x;

    float m1 = -1e30f, m2 = -1e30f;
    for (int i = tid; i < NB; i += 1024) {
        float cx = boxes[i * 5 + 0], cy = boxes[i * 5 + 1];
        float w  = boxes[i * 5 + 2], h  = boxes[i * 5 + 3];
        float s  = __fsqrt_rn(xadd(xmul(w, w), xmul(h, h)));
        m1 = fmaxf(m1, s);
        m2 = fmaxf(m2, fmaxf(cx, cy));
    }
    red[tid] = m1; __syncthreads();
    for (int s = 512; s > 0; s >>= 1) { if (tid < s) red[tid] = fmaxf(red[tid], red[tid + s]); __syncthreads(); }
    float maxs = red[0]; __syncthreads();
    red[tid] = m2; __syncthreads();
    for (int s = 512; s > 0; s >>= 1) { if (tid < s) red[tid] = fmaxf(red[tid], red[tid + s]); __syncthreads(); }
    float maxc = red[0];

    if (tid == 0) {
        float max_radius = xmul(maxs, 0.5f);
        float t = xadd(maxc, max_radius);
        g_scale = xadd(xmul(t, 2.0f), 1.0f);   // (max_coord + max_radius)*2 + 1
        g_paircnt = 0;
    }
    if (tid < NWORDS) g_rownz[tid] = 0ULL;
    for (int i = tid; i < NB; i += 1024) {
        unsigned int sb = __float_as_uint(scores[i]);  // scores >= 0 -> monotone bits
        g_keys[i] = ((u64)(sb ^ 0xFFFFFFFFu) << 32) | (u32)i;
    }
}

// ---------------- kernel A2: rank (4 threads/box) + precompute into sorted slot ----------------
__global__ void __launch_bounds__(128) rank_prep_kernel(const float* __restrict__ boxes,
                                                        const int*   __restrict__ labels) {
    __shared__ u64 skeys[NB];
    const int tid = threadIdx.x;
    for (int q = tid; q < NB; q += 128) skeys[q] = g_keys[q];
    __syncthreads();

    const int gt   = blockIdx.x * 128 + tid;   // 8192 threads total
    const int i    = gt >> 2;                  // original box index
    const int part = gt & 3;                   // which quarter of keys to scan
    const u64 mykey = skeys[i];

    int rank = 0;
    const int q0 = part * (NB / 4);
#pragma unroll 8
    for (int q = 0; q < NB / 4; q++) rank += (skeys[q0 + q] < mykey);
    rank += __shfl_xor_sync(0xFFFFFFFFu, rank, 1);
    rank += __shfl_xor_sync(0xFFFFFFFFu, rank, 2);
    if (part != 0) return;

    const float scale = g_scale;
    float off = xmul((float)labels[i], scale);
    float cx = xadd(boxes[i * 5 + 0], off);
    float cy = xadd(boxes[i * 5 + 1], off);
    float w  = boxes[i * 5 + 2];
    float h  = boxes[i * 5 + 3];
    float a  = boxes[i * 5 + 4];
    float c  = (float)cos((double)a);        // correctly-rounded fp32 trig
    float s  = (float)sin((double)a);
    float wh = xmul(w, 0.5f);
    float hh = xmul(h, 0.5f);

    float* P = &g_pboxs[rank * 16];
#pragma unroll
    for (int q = 0; q < 4; q++) {
        float dx = (q == 1 || q == 2) ? wh : -wh;
        float dy = (q >= 2) ? hh : -hh;
        P[q]     = xsub(xadd(cx, xmul(c, dx)), xmul(s, dy));
        P[4 + q] = xadd(xadd(cy, xmul(s, dx)), xmul(c, dy));
    }
    P[8]  = cx;  P[9]  = cy;  P[10] = c;  P[11] = s;
    P[12] = xadd(wh, 1e-5f);
    P[13] = xadd(hh, 1e-5f);
    P[14] = xmul(w, h);
    P[15] = 0.5f * __fsqrt_rn(w * w + h * h) + 1e-2f;   // conservative circle radius
    g_order[rank] = i;
}

// ---------------- kernel B1: circle filter -> pair list, zero mask ----------------
__global__ void __launch_bounds__(64) pair_filter_kernel() {
    const int by = blockIdx.y, bx = blockIdx.x;
    if (bx < by) return;                      // lower-triangle words are never written; stay 0
    const int t = threadIdx.x;
    const int i = by * 64 + t;

    g_mask[i * NWORDS + bx] = 0ULL;

    __shared__ float scx[64], scy[64], srad[64];
    int col0 = bx * 64 + t;
    scx[t]  = g_pboxs[col0 * 16 + 8];
    scy[t]  = g_pboxs[col0 * 16 + 9];
    srad[t] = g_pboxs[col0 * 16 + 15];
    __syncthreads();

    const float acx = g_pboxs[i * 16 + 8];
    const float acy = g_pboxs[i * 16 + 9];
    const float ard = g_pboxs[i * 16 + 15];

    for (int j = 0; j < 64; j++) {
        int col = bx * 64 + j;
        if (col <= i) continue;
        float dx = acx - scx[j], dy = acy - scy[j];
        float rr = ard + srad[j];
        if (dx * dx + dy * dy > rr * rr) continue;   // disjoint -> inter == 0 exactly
        int idx = atomicAdd(&g_paircnt, 1);
        if (idx < MAXPAIRS) g_pairs[idx] = ((u32)i << 11) | (u32)col;
    }
}

// ---------------- exact-replica pairwise intersection area (compacted) ----------------
__device__ __forceinline__ bool pib(float x, float y, const float* __restrict__ B) {
    float px = xsub(x, B[8]);
    float py = xsub(y, B[9]);
    float lx = xadd(xmul(B[10], px), xmul(B[11], py));     //  c*px + s*py
    float ly = xadd(xmul(-B[11], px), xmul(B[10], py));    // -s*px + c*py
    return (fabsf(lx) <= B[12]) && (fabsf(ly) <= B[13]);
}

__device__ float pair_inter_area(const float* __restrict__ A, const float* __restrict__ B) {
    float px[24], py[24];
    int k = 0;
    float sxm = 0.0f, sym = 0.0f;

    // candidate points appended in reference index order 0..23 -> identical fp sum order
#pragma unroll
    for (int q = 0; q < 4; q++) {
        if (pib(A[q], A[4 + q], B)) {
            px[k] = A[q]; py[k] = A[4 + q];
            sxm = xadd(sxm, A[q]); sym = xadd(sym, A[4 + q]); k++;
        }
    }
#pragma unroll
    for (int q = 0; q < 4; q++) {
        if (pib(B[q], B[4 + q], A)) {
            px[k] = B[q]; py[k] = B[4 + q];
            sxm = xadd(sxm, B[q]); sym = xadd(sym, B[4 + q]); k++;
        }
    }
#pragma unroll
    for (int ea = 0; ea < 4; ea++) {
        float pxx = A[ea], pyy = A[4 + ea];
        float rx = xsub(A[(ea + 1) & 3], pxx), ry = xsub(A[4 + ((ea + 1) & 3)], pyy);
#pragma unroll
        for (int eb = 0; eb < 4; eb++) {
            float qx = B[eb], qy = B[4 + eb];
            float sx = xsub(B[(eb + 1) & 3], qx), sy = xsub(B[4 + ((eb + 1) & 3)], qy);
            float den = xcross(rx, ry, sx, sy);
            float qpx = xsub(qx, pxx), qpy = xsub(qy, pyy);
            if (fabsf(den) > 1e-9f) {
                float tt = xdiv(xcross(qpx, qpy, sx, sy), den);
                float uu = xdiv(xcross(qpx, qpy, rx, ry), den);
                if (tt >= 0.0f && tt <= 1.0f && uu >= 0.0f && uu <= 1.0f) {
                    float ix = xadd(pxx, xmul(tt, rx));
                    float iy = xadd(pyy, xmul(tt, ry));
                    px[k] = ix; py[k] = iy;
                    sxm = xadd(sxm, ix); sym = xadd(sym, iy); k++;
                }
            }
        }
    }
    if (k < 3) return 0.0f;

    float kk  = (float)k;
    float cxm = xdiv(sxm, kk), cym = xdiv(sym, kk);

    float dxr[24], dyr[24];
    u64 key[24];
    for (int q = 0; q < k; q++) {
        float dx = xsub(px[q], cxm);
        float dy = xsub(py[q], cym);
        dxr[q] = dx; dyr[q] = dy;
        float a = atan2f(dy, dx);
        u32 b = __float_as_uint(a);
        b = (b & 0x80000000u) ? ~b : (b | 0x80000000u);   // monotone map
        key[q] = ((u64)b << 5) | (u32)q;                   // unique -> stable order
    }
    // insertion sort on k elements (k typically 4-8)
    for (int q = 1; q < k; q++) {
        u64 kq = key[q]; int r = q - 1;
        while (r >= 0 && key[r] > kq) { key[r + 1] = key[r]; r--; }
        key[r + 1] = kq;
    }

    float tot = 0.0f;
    for (int q = 0; q < k; q++) {
        int nq = (q + 1 < k) ? q + 1 : 0;
        int a0 = (int)(key[q]  & 31u);
        int a1 = (int)(key[nq] & 31u);
        tot = xadd(tot, xcross(dxr[a0], dyr[a0], dxr[a1], dyr[a1]));
    }
    return xmul(0.5f, fabsf(tot));
}

// ---------------- kernel B2: one expensive pair per thread, lane-spread ----------------
__global__ void __launch_bounds__(256) pair_iou_kernel(const float* __restrict__ thrp) {
    const int cnt = g_paircnt;
    const float thr = thrp[0];
    const int G = gridDim.x;
    const int w = threadIdx.x >> 5, l = threadIdx.x & 31;
    const int stride = G * 256;

    // pair p -> block p%G, warp (p/G)%8, lane p/(8G): spreads small cnt across all warps
    for (int idx = blockIdx.x + G * (w + 8 * l); idx < cnt; idx += stride) {
        u32 p = g_pairs[idx];
        int i = (int)(p >> 11), j = (int)(p & 0x7FFu);

        float A[16], B[16];
        const float4* Ap = (const float4*)&g_pboxs[i * 16];
        const float4* Bp = (const float4*)&g_pboxs[j * 16];
#pragma unroll
        for (int q = 0; q < 4; q++) {
            float4 va = Ap[q], vb = Bp[q];
            A[q*4+0]=va.x; A[q*4+1]=va.y; A[q*4+2]=va.z; A[q*4+3]=va.w;
            B[q*4+0]=vb.x; B[q*4+1]=vb.y; B[q*4+2]=vb.z; B[q*4+3]=vb.w;
        }
        float inter = pair_inter_area(A, B);
        float iou = xdiv(inter, xadd(xsub(xadd(A[14], B[14]), inter), 1e-9f));
        if (iou > thr) {
            atomicOr(&g_mask[i * NWORDS + (j >> 6)], 1ULL << (j & 63));
            atomicOr(&g_rownz[i >> 6], 1ULL << (i & 63));
        }
    }
}

// ---------------- kernel C: bitmap-sparse greedy scan + output ----------------
__device__ __forceinline__ u64 morton_even(u32 x) {
    u64 v = x;
    v = (v | (v << 16)) & 0x0000FFFF0000FFFFULL;
    v = (v | (v << 8))  & 0x00FF00FF00FF00FFULL;
    v = (v | (v << 4))  & 0x0F0F0F0F0F0F0F0FULL;
    v = (v | (v << 2))  & 0x3333333333333333ULL;
    v = (v | (v << 1))  & 0x5555555555555555ULL;
    return v;
}

__global__ void __launch_bounds__(32) scan_kernel(const float* __restrict__ scores,
                                                  float* __restrict__ out) {
    __shared__ u64 sdiag[NB];          // 16KB: each box's diagonal-block word
    __shared__ u64 snz[NWORDS];
    __shared__ u64 s_keep[NWORDS];
    const int lane = threadIdx.x;

    for (int i = lane; i < NB; i += 32)
        sdiag[i] = g_mask[i * NWORDS + (i >> 6)];
    snz[lane] = g_rownz[lane];
    __syncwarp();

    u64 rem = 0ULL;   // lane's suppression word
    for (int c = 0; c < NWORDS; c++) {
        u64 cur = __shfl_sync(0xFFFFFFFFu, rem, c);

        // bitmap of rows in this chunk with nonzero diagonal word
        u64 w0 = sdiag[c * 64 + lane * 2];
        u64 w1 = sdiag[c * 64 + lane * 2 + 1];
        u32 b0 = __ballot_sync(0xFFFFFFFFu, w0 != 0ULL);
        u32 b1 = __ballot_sync(0xFFFFFFFFu, w1 != 0ULL);
        u64 nzd = morton_even(b0) | (morton_even(b1) << 1);

        // sparse serial resolve (all lanes redundantly; smem broadcast)
        u64 A = 0ULL, covered = 0ULL;
        u64 m = nzd;
        while (m) {
            int pbit = __ffsll((long long)m) - 1; m &= m - 1;
            u64 range = ((2ULL << pbit) - 1ULL) & ~covered;   // bits [0..pbit] not yet covered
            A |= (~cur) & range;
            covered |= range;
            if ((A >> pbit) & 1ULL) cur |= sdiag[c * 64 + pbit];
        }
        A |= (~cur) & ~covered;

        // OR full rows of alive suppressors (few): coalesced 256B L2 loads
        u64 need = A & snz[c];
        while (need) {
            int j = __ffsll((long long)need) - 1; need &= need - 1;
            rem |= g_mask[(u32)(c * 64 + j) * NWORDS + lane];
        }
        if (lane == 0) s_keep[c] = A;
    }
    __syncwarp();

    for (int i = lane; i < NB; i += 32) {
        int keep = (int)((s_keep[i >> 6] >> (i & 63)) & 1ULL);
        int orig = g_order[i];
        out[orig] = keep ? scores[orig] : 0.0f;
    }
}

// ---------------- launch ----------------
extern "C" void kernel_launch(void* const* d_in, const int* in_sizes, int n_in,
                              void* d_out, int out_size) {
    (void)in_sizes; (void)n_in; (void)out_size;
    const float* boxes  = (const float*)d_in[0];
    const float* scores = (const float*)d_in[1];
    const int*   labels = (const int*)d_in[2];
    const float* thr    = (const float*)d_in[3];
    float* out = (float*)d_out;

    reduce_keys_kernel<<<1, 1024>>>(boxes, scores);
    rank_prep_kernel<<<(NB * 4) / 128, 128>>>(boxes, labels);
    pair_filter_kernel<<<dim3(NWORDS, NWORDS), 64>>>();
    pair_iou_kernel<<<148, 256>>>(thr);
    scan_kernel<<<1, 32>>>(scores, out);
}

// round 4
// speedup vs baseline: 4.5022x; 1.4132x over previous
#include <cuda_runtime.h>
#include <cstdint>

#define NB 2048
#define NWORDS (NB / 64)          // 32

typedef unsigned long long u64;
typedef unsigned int u32;
typedef unsigned short u16;

// ---------------- device scratch ----------------
__device__ int   g_order[NB];              // sorted pos -> original index
__device__ float g_pboxs[NB * 16];         // SORTED: x0..3,y0..3,cx,cy,c,s,we,he,area,rad
__device__ u64   g_mask[NB * NWORDS];      // suppression bitmask (sorted order); lower-tri never written, stays 0
__device__ u64   g_rownz[NWORDS];          // bit j of word c -> row c*64+j has any suppression

// exact (non-contracted) fp32 helpers — replicate jax/XLA unfused fp32 ops
__device__ __forceinline__ float xmul(float a, float b) { return __fmul_rn(a, b); }
__device__ __forceinline__ float xadd(float a, float b) { return __fadd_rn(a, b); }
__device__ __forceinline__ float xsub(float a, float b) { return __fsub_rn(a, b); }
__device__ __forceinline__ float xdiv(float a, float b) { return __fdiv_rn(a, b); }
__device__ __forceinline__ float xcross(float ax, float ay, float bx, float by) {
    return xsub(xmul(ax, by), xmul(ay, bx));
}

// ---------------- kernel 1: fused reduce + keys + rank + precompute ----------------
// 64 blocks x 128 threads; 4 threads per box. Each block redundantly does the
// global reductions + key build (cheap) so no separate kernel / global keys.
__global__ void __launch_bounds__(128) prep_kernel(const float* __restrict__ boxes,
                                                   const float* __restrict__ scores,
                                                   const int*   __restrict__ labels) {
    __shared__ u32  skeys[NB];
    __shared__ float red[128];
    const int tid = threadIdx.x;

    float m1 = -1e30f, m2 = -1e30f;
    for (int q = tid; q < NB; q += 128) {
        float cx = boxes[q * 5 + 0], cy = boxes[q * 5 + 1];
        float w  = boxes[q * 5 + 2], h  = boxes[q * 5 + 3];
        float s  = __fsqrt_rn(xadd(xmul(w, w), xmul(h, h)));
        m1 = fmaxf(m1, s);
        m2 = fmaxf(m2, fmaxf(cx, cy));
        skeys[q] = __float_as_uint(scores[q]) ^ 0xFFFFFFFFu;   // ascending == descending score
    }
    red[tid] = m1; __syncthreads();
    for (int s = 64; s > 0; s >>= 1) { if (tid < s) red[tid] = fmaxf(red[tid], red[tid + s]); __syncthreads(); }
    float maxs = red[0]; __syncthreads();
    red[tid] = m2; __syncthreads();
    for (int s = 64; s > 0; s >>= 1) { if (tid < s) red[tid] = fmaxf(red[tid], red[tid + s]); __syncthreads(); }
    float maxc = red[0];

    // scale = (max_coord + max_radius)*2 + 1  (exact ref fp32 sequence)
    float scale = xadd(xmul(xadd(maxc, xmul(maxs, 0.5f)), 2.0f), 1.0f);

    if (blockIdx.x == 0 && tid < NWORDS) g_rownz[tid] = 0ULL;

    const int gt   = blockIdx.x * 128 + tid;   // 8192 threads
    const int i    = gt >> 2;                  // original box index
    const int part = gt & 3;
    const u32 mykey = skeys[i];

    int rank = 0;
    const int q0 = part * (NB / 4);
#pragma unroll 8
    for (int q = 0; q < NB / 4; q++) {
        u32 kq = skeys[q0 + q];
        rank += (kq < mykey) || (kq == mykey && (q0 + q) < i);   // stable tiebreak
    }
    rank += __shfl_xor_sync(0xFFFFFFFFu, rank, 1);
    rank += __shfl_xor_sync(0xFFFFFFFFu, rank, 2);
    if (part != 0) return;

    float off = xmul((float)labels[i], scale);
    float cx = xadd(boxes[i * 5 + 0], off);
    float cy = xadd(boxes[i * 5 + 1], off);
    float w  = boxes[i * 5 + 2];
    float h  = boxes[i * 5 + 3];
    float a  = boxes[i * 5 + 4];
    float c  = (float)cos((double)a);        // correctly-rounded fp32 trig
    float s  = (float)sin((double)a);
    float wh = xmul(w, 0.5f);
    float hh = xmul(h, 0.5f);

    float* P = &g_pboxs[rank * 16];
#pragma unroll
    for (int q = 0; q < 4; q++) {
        float dx = (q == 1 || q == 2) ? wh : -wh;
        float dy = (q >= 2) ? hh : -hh;
        P[q]     = xsub(xadd(cx, xmul(c, dx)), xmul(s, dy));
        P[4 + q] = xadd(xadd(cy, xmul(s, dx)), xmul(c, dy));
    }
    P[8]  = cx;  P[9]  = cy;  P[10] = c;  P[11] = s;
    P[12] = xadd(wh, 1e-5f);
    P[13] = xadd(hh, 1e-5f);
    P[14] = xmul(w, h);
    P[15] = 0.5f * __fsqrt_rn(w * w + h * h) + 1e-2f;   // conservative circle radius
    g_order[rank] = i;
}

// ---------------- exact-replica pairwise intersection area (compacted) ----------------
__device__ __forceinline__ bool pib(float x, float y, const float* __restrict__ B) {
    float px = xsub(x, B[8]);
    float py = xsub(y, B[9]);
    float lx = xadd(xmul(B[10], px), xmul(B[11], py));     //  c*px + s*py
    float ly = xadd(xmul(-B[11], px), xmul(B[10], py));    // -s*px + c*py
    return (fabsf(lx) <= B[12]) && (fabsf(ly) <= B[13]);
}

__device__ float pair_inter_area(const float* __restrict__ A, const float* __restrict__ B) {
    float px[24], py[24];
    int k = 0;
    float sxm = 0.0f, sym = 0.0f;

    // candidate points appended in reference index order 0..23 -> identical fp sum order
#pragma unroll
    for (int q = 0; q < 4; q++) {
        if (pib(A[q], A[4 + q], B)) {
            px[k] = A[q]; py[k] = A[4 + q];
            sxm = xadd(sxm, A[q]); sym = xadd(sym, A[4 + q]); k++;
        }
    }
#pragma unroll
    for (int q = 0; q < 4; q++) {
        if (pib(B[q], B[4 + q], A)) {
            px[k] = B[q]; py[k] = B[4 + q];
            sxm = xadd(sxm, B[q]); sym = xadd(sym, B[4 + q]); k++;
        }
    }
#pragma unroll
    for (int ea = 0; ea < 4; ea++) {
        float pxx = A[ea], pyy = A[4 + ea];
        float rx = xsub(A[(ea + 1) & 3], pxx), ry = xsub(A[4 + ((ea + 1) & 3)], pyy);
#pragma unroll
        for (int eb = 0; eb < 4; eb++) {
            float qx = B[eb], qy = B[4 + eb];
            float sx = xsub(B[(eb + 1) & 3], qx), sy = xsub(B[4 + ((eb + 1) & 3)], qy);
            float den = xcross(rx, ry, sx, sy);
            float qpx = xsub(qx, pxx), qpy = xsub(qy, pyy);
            if (fabsf(den) > 1e-9f) {
                float tt = xdiv(xcross(qpx, qpy, sx, sy), den);
                float uu = xdiv(xcross(qpx, qpy, rx, ry), den);
                if (tt >= 0.0f && tt <= 1.0f && uu >= 0.0f && uu <= 1.0f) {
                    float ix = xadd(pxx, xmul(tt, rx));
                    float iy = xadd(pyy, xmul(tt, ry));
                    px[k] = ix; py[k] = iy;
                    sxm = xadd(sxm, ix); sym = xadd(sym, iy); k++;
                }
            }
        }
    }
    if (k < 3) return 0.0f;

    float kk  = (float)k;
    float cxm = xdiv(sxm, kk), cym = xdiv(sym, kk);

    float dxr[24], dyr[24];
    u64 key[24];
    for (int q = 0; q < k; q++) {
        float dx = xsub(px[q], cxm);
        float dy = xsub(py[q], cym);
        dxr[q] = dx; dyr[q] = dy;
        float a = atan2f(dy, dx);
        u32 b = __float_as_uint(a);
        b = (b & 0x80000000u) ? ~b : (b | 0x80000000u);   // monotone map
        key[q] = ((u64)b << 5) | (u32)q;                   // unique -> stable order
    }
    for (int q = 1; q < k; q++) {          // insertion sort, k typically 4-8
        u64 kq = key[q]; int r = q - 1;
        while (r >= 0 && key[r] > kq) { key[r + 1] = key[r]; r--; }
        key[r + 1] = kq;
    }

    float tot = 0.0f;
    for (int q = 0; q < k; q++) {
        int nq = (q + 1 < k) ? q + 1 : 0;
        int a0 = (int)(key[q]  & 31u);
        int a1 = (int)(key[nq] & 31u);
        tot = xadd(tot, xcross(dxr[a0], dyr[a0], dxr[a1], dyr[a1]));
    }
    return xmul(0.5f, fabsf(tot));
}

// ---------------- kernel 2: fused circle-filter + IoU per 64x64 tile ----------------
__global__ void __launch_bounds__(64) mask_kernel(const float* __restrict__ thrp) {
    const int by = blockIdx.y, bx = blockIdx.x;
    if (bx < by) return;                  // lower-triangle words never written (stay 0)
    const int t = threadIdx.x;
    const int i = by * 64 + t;

    __shared__ __align__(16) float sB[64 * 16];   // col tile boxes
    __shared__ u64 sbits[64];
    __shared__ u16 queue[4096];                   // worst case 64*64 local pairs
    __shared__ int qcnt;

    for (int q = t; q < 64 * 16; q += 64) sB[q] = g_pboxs[bx * 64 * 16 + q];
    sbits[t] = 0ULL;
    if (t == 0) qcnt = 0;
    __syncthreads();

    const float acx = g_pboxs[i * 16 + 8];
    const float acy = g_pboxs[i * 16 + 9];
    const float ard = g_pboxs[i * 16 + 15];

    const int jstart = (bx == by) ? (t + 1) : 0;   // ensures col > i
    for (int j = jstart; j < 64; j++) {
        float dx = acx - sB[j * 16 + 8], dy = acy - sB[j * 16 + 9];
        float rr = ard + sB[j * 16 + 15];
        if (dx * dx + dy * dy <= rr * rr) {        // circle overlap -> candidate
            int q = atomicAdd(&qcnt, 1);
            queue[q] = (u16)((t << 6) | j);
        }
    }
    __syncthreads();

    const int n = qcnt;
    const float thr = thrp[0];
    for (int q = t; q < n; q += 64) {
        u16 v = queue[q];
        int ti = v >> 6, j = v & 63;

        float A[16], B[16];
        const float4* Ap = (const float4*)&g_pboxs[(by * 64 + ti) * 16];
        const float4* Bp = (const float4*)&sB[j * 16];
#pragma unroll
        for (int r = 0; r < 4; r++) {
            float4 va = Ap[r], vb = Bp[r];
            A[r*4+0]=va.x; A[r*4+1]=va.y; A[r*4+2]=va.z; A[r*4+3]=va.w;
            B[r*4+0]=vb.x; B[r*4+1]=vb.y; B[r*4+2]=vb.z; B[r*4+3]=vb.w;
        }
        float inter = pair_inter_area(A, B);
        float iou = xdiv(inter, xadd(xsub(xadd(A[14], B[14]), inter), 1e-9f));
        if (iou > thr) atomicOr(&sbits[ti], 1ULL << j);
    }
    __syncthreads();

    g_mask[i * NWORDS + bx] = sbits[t];            // block exclusively owns these words
    if (sbits[t]) atomicOr(&g_rownz[by], 1ULL << t);
}

// ---------------- kernel 3: bitmap-sparse greedy scan + output ----------------
__device__ __forceinline__ u64 morton_even(u32 x) {
    u64 v = x;
    v = (v | (v << 16)) & 0x0000FFFF0000FFFFULL;
    v = (v | (v << 8))  & 0x00FF00FF00FF00FFULL;
    v = (v | (v << 4))  & 0x0F0F0F0F0F0F0F0FULL;
    v = (v | (v << 2))  & 0x3333333333333333ULL;
    v = (v | (v << 1))  & 0x5555555555555555ULL;
    return v;
}

__global__ void __launch_bounds__(128) scan_kernel(const float* __restrict__ scores,
                                                   float* __restrict__ out) {
    __shared__ u64 sdiag[NB];          // 16KB: each box's diagonal-block word
    __shared__ u64 snz[NWORDS];
    __shared__ u64 s_keep[NWORDS];
    const int tid = threadIdx.x;

    for (int i = tid; i < NB; i += 128)
        sdiag[i] = g_mask[i * NWORDS + (i >> 6)];
    if (tid < NWORDS) snz[tid] = g_rownz[tid];
    __syncthreads();

    if (tid < 32) {
        const int lane = tid;
        u64 rem = 0ULL;   // lane's suppression word
        for (int c = 0; c < NWORDS; c++) {
            u64 cur = __shfl_sync(0xFFFFFFFFu, rem, c);

            u64 w0 = sdiag[c * 64 + lane * 2];
            u64 w1 = sdiag[c * 64 + lane * 2 + 1];
            u32 b0 = __ballot_sync(0xFFFFFFFFu, w0 != 0ULL);
            u32 b1 = __ballot_sync(0xFFFFFFFFu, w1 != 0ULL);
            u64 nzd = morton_even(b0) | (morton_even(b1) << 1);

            // sparse serial resolve (all lanes redundantly; smem broadcast)
            u64 A = 0ULL, covered = 0ULL;
            u64 m = nzd;
            while (m) {
                int pbit = __ffsll((long long)m) - 1; m &= m - 1;
                u64 range = ((2ULL << pbit) - 1ULL) & ~covered;
                A |= (~cur) & range;
                covered |= range;
                if ((A >> pbit) & 1ULL) cur |= sdiag[c * 64 + pbit];
            }
            A |= (~cur) & ~covered;

            // OR full rows of alive suppressors: coalesced 256B L2 loads
            u64 need = A & snz[c];
            while (need) {
                int j = __ffsll((long long)need) - 1; need &= need - 1;
                rem |= g_mask[(u32)(c * 64 + j) * NWORDS + lane];
            }
            if (lane == 0) s_keep[c] = A;
        }
    }
    __syncthreads();

    for (int i = tid; i < NB; i += 128) {
        int keep = (int)((s_keep[i >> 6] >> (i & 63)) & 1ULL);
        int orig = g_order[i];
        out[orig] = keep ? scores[orig] : 0.0f;
    }
}

// ---------------- launch ----------------
extern "C" void kernel_launch(void* const* d_in, const int* in_sizes, int n_in,
                              void* d_out, int out_size) {
    (void)in_sizes; (void)n_in; (void)out_size;
    const float* boxes  = (const float*)d_in[0];
    const float* scores = (const float*)d_in[1];
    const int*   labels = (const int*)d_in[2];
    const float* thr    = (const float*)d_in[3];
    float* out = (float*)d_out;

    prep_kernel<<<(NB * 4) / 128, 128>>>(boxes, scores, labels);
    mask_kernel<<<dim3(NWORDS, NWORDS), 64>>>(thr);
    scan_kernel<<<1, 128>>>(scores, out);
}

// round 5
// speedup vs baseline: 5.1913x; 1.1531x over previous
#include <cuda_runtime.h>
#include <cstdint>

#define NB 2048
#define NWORDS (NB / 64)          // 32
#define NTILES (NWORDS * (NWORDS + 1) / 2)   // 528 upper-tri blocks

typedef unsigned long long u64;
typedef unsigned int u32;
typedef unsigned short u16;

// ---------------- device scratch ----------------
__device__ int   g_order[NB];              // sorted pos -> original index
__device__ float g_pboxs[NB * 16];         // SORTED: x0..3,y0..3,cx,cy,c,s,we,he,area,rad
__device__ u64   g_mask[NB * NWORDS];      // suppression bitmask; lower-tri never written, stays 0
__device__ u64   g_diag[NB];               // each row's diagonal-block word (contiguous copy)
__device__ u64   g_rownz[NWORDS];          // bit j of word c -> row c*64+j has any suppression
__device__ int   g_done;

// exact (non-contracted) fp32 helpers — replicate jax/XLA unfused fp32 ops
__device__ __forceinline__ float xmul(float a, float b) { return __fmul_rn(a, b); }
__device__ __forceinline__ float xadd(float a, float b) { return __fadd_rn(a, b); }
__device__ __forceinline__ float xsub(float a, float b) { return __fsub_rn(a, b); }
__device__ __forceinline__ float xdiv(float a, float b) { return __fdiv_rn(a, b); }
__device__ __forceinline__ float xcross(float ax, float ay, float bx, float by) {
    return xsub(xmul(ax, by), xmul(ay, bx));
}

// ---------------- kernel 1: fused reduce + keys + rank + precompute ----------------
// 256 blocks x 256 threads; 32 threads (one warp) per box.
__global__ void __launch_bounds__(256) prep_kernel(const float* __restrict__ boxes,
                                                   const float* __restrict__ scores,
                                                   const int*   __restrict__ labels) {
    __shared__ u32  skeys[NB];
    __shared__ float red[256];
    const int tid = threadIdx.x;

    // m1 tracks max (w*w+h*h); sqrt is correctly rounded (monotone), so
    // max_i sqrt(x_i) == sqrt(max_i x_i) bit-exactly.
    float m1 = -1e30f, m2 = -1e30f;
    for (int q = tid; q < NB; q += 256) {
        float cx = boxes[q * 5 + 0], cy = boxes[q * 5 + 1];
        float w  = boxes[q * 5 + 2], h  = boxes[q * 5 + 3];
        float s2 = xadd(xmul(w, w), xmul(h, h));
        m1 = fmaxf(m1, s2);
        m2 = fmaxf(m2, fmaxf(cx, cy));
        skeys[q] = __float_as_uint(scores[q]) ^ 0xFFFFFFFFu;   // ascending == descending score
    }
    red[tid] = m1; __syncthreads();
    for (int s = 128; s > 0; s >>= 1) { if (tid < s) red[tid] = fmaxf(red[tid], red[tid + s]); __syncthreads(); }
    float maxs = __fsqrt_rn(red[0]); __syncthreads();
    red[tid] = m2; __syncthreads();
    for (int s = 128; s > 0; s >>= 1) { if (tid < s) red[tid] = fmaxf(red[tid], red[tid + s]); __syncthreads(); }
    float maxc = red[0];

    // scale = (max_coord + max_radius)*2 + 1  (exact ref fp32 sequence)
    float scale = xadd(xmul(xadd(maxc, xmul(maxs, 0.5f)), 2.0f), 1.0f);

    if (blockIdx.x == 0) {
        if (tid < NWORDS) g_rownz[tid] = 0ULL;
        if (tid == 0) g_done = 0;
    }

    const int gt   = blockIdx.x * 256 + tid;   // 65536 threads
    const int i    = gt >> 5;                  // original box index
    const int lane = gt & 31;
    const u32 mykey = skeys[i];

    int rank = 0;
    const int q0 = lane * (NB / 32);
#pragma unroll 16
    for (int q = 0; q < NB / 32; q++) {
        u32 kq = skeys[q0 + q];
        rank += (kq < mykey) || (kq == mykey && (q0 + q) < i);   // stable tiebreak
    }
#pragma unroll
    for (int off = 16; off > 0; off >>= 1) rank += __shfl_xor_sync(0xFFFFFFFFu, rank, off);
    if (lane != 0) return;

    float off = xmul((float)labels[i], scale);
    float cx = xadd(boxes[i * 5 + 0], off);
    float cy = xadd(boxes[i * 5 + 1], off);
    float w  = boxes[i * 5 + 2];
    float h  = boxes[i * 5 + 3];
    float a  = boxes[i * 5 + 4];
    float c  = (float)cos((double)a);        // correctly-rounded fp32 trig
    float s  = (float)sin((double)a);
    float wh = xmul(w, 0.5f);
    float hh = xmul(h, 0.5f);

    float* P = &g_pboxs[rank * 16];
#pragma unroll
    for (int q = 0; q < 4; q++) {
        float dx = (q == 1 || q == 2) ? wh : -wh;
        float dy = (q >= 2) ? hh : -hh;
        P[q]     = xsub(xadd(cx, xmul(c, dx)), xmul(s, dy));
        P[4 + q] = xadd(xadd(cy, xmul(s, dx)), xmul(c, dy));
    }
    P[8]  = cx;  P[9]  = cy;  P[10] = c;  P[11] = s;
    P[12] = xadd(wh, 1e-5f);
    P[13] = xadd(hh, 1e-5f);
    P[14] = xmul(w, h);
    P[15] = 0.5f * __fsqrt_rn(w * w + h * h) + 1e-2f;   // conservative circle radius
    g_order[rank] = i;
}

// ---------------- exact-replica pairwise intersection area (compacted) ----------------
__device__ __forceinline__ bool pib(float x, float y, const float* __restrict__ B) {
    float px = xsub(x, B[8]);
    float py = xsub(y, B[9]);
    float lx = xadd(xmul(B[10], px), xmul(B[11], py));     //  c*px + s*py
    float ly = xadd(xmul(-B[11], px), xmul(B[10], py));    // -s*px + c*py
    return (fabsf(lx) <= B[12]) && (fabsf(ly) <= B[13]);
}

__device__ float pair_inter_area(const float* __restrict__ A, const float* __restrict__ B) {
    float px[24], py[24];
    int k = 0;
    float sxm = 0.0f, sym = 0.0f;

    // candidate points appended in reference index order 0..23 -> identical fp sum order
#pragma unroll
    for (int q = 0; q < 4; q++) {
        if (pib(A[q], A[4 + q], B)) {
            px[k] = A[q]; py[k] = A[4 + q];
            sxm = xadd(sxm, A[q]); sym = xadd(sym, A[4 + q]); k++;
        }
    }
#pragma unroll
    for (int q = 0; q < 4; q++) {
        if (pib(B[q], B[4 + q], A)) {
            px[k] = B[q]; py[k] = B[4 + q];
            sxm = xadd(sxm, B[q]); sym = xadd(sym, B[4 + q]); k++;
        }
    }
#pragma unroll
    for (int ea = 0; ea < 4; ea++) {
        float pxx = A[ea], pyy = A[4 + ea];
        float rx = xsub(A[(ea + 1) & 3], pxx), ry = xsub(A[4 + ((ea + 1) & 3)], pyy);
#pragma unroll
        for (int eb = 0; eb < 4; eb++) {
            float qx = B[eb], qy = B[4 + eb];
            float sx = xsub(B[(eb + 1) & 3], qx), sy = xsub(B[4 + ((eb + 1) & 3)], qy);
            float den = xcross(rx, ry, sx, sy);
            float qpx = xsub(qx, pxx), qpy = xsub(qy, pyy);
            if (fabsf(den) > 1e-9f) {
                float tt = xdiv(xcross(qpx, qpy, sx, sy), den);
                float uu = xdiv(xcross(qpx, qpy, rx, ry), den);
                if (tt >= 0.0f && tt <= 1.0f && uu >= 0.0f && uu <= 1.0f) {
                    float ix = xadd(pxx, xmul(tt, rx));
                    float iy = xadd(pyy, xmul(tt, ry));
                    px[k] = ix; py[k] = iy;
                    sxm = xadd(sxm, ix); sym = xadd(sym, iy); k++;
                }
            }
        }
    }
    if (k < 3) return 0.0f;

    float kk  = (float)k;
    float cxm = xdiv(sxm, kk), cym = xdiv(sym, kk);

    float dxr[24], dyr[24];
    u64 key[24];
    for (int q = 0; q < k; q++) {
        float dx = xsub(px[q], cxm);
        float dy = xsub(py[q], cym);
        dxr[q] = dx; dyr[q] = dy;
        float a = atan2f(dy, dx);
        u32 b = __float_as_uint(a);
        b = (b & 0x80000000u) ? ~b : (b | 0x80000000u);   // monotone map
        key[q] = ((u64)b << 5) | (u32)q;                   // unique -> stable order
    }
    for (int q = 1; q < k; q++) {          // insertion sort, k typically 4-8
        u64 kq = key[q]; int r = q - 1;
        while (r >= 0 && key[r] > kq) { key[r + 1] = key[r]; r--; }
        key[r + 1] = kq;
    }

    float tot = 0.0f;
    for (int q = 0; q < k; q++) {
        int nq = (q + 1 < k) ? q + 1 : 0;
        int a0 = (int)(key[q]  & 31u);
        int a1 = (int)(key[nq] & 31u);
        tot = xadd(tot, xcross(dxr[a0], dyr[a0], dxr[a1], dyr[a1]));
    }
    return xmul(0.5f, fabsf(tot));
}

// ---------------- kernel 2: fused filter + IoU + (last block) greedy scan ----------------
__device__ __forceinline__ u64 morton_even(u32 x) {
    u64 v = x;
    v = (v | (v << 16)) & 0x0000FFFF0000FFFFULL;
    v = (v | (v << 8))  & 0x00FF00FF00FF00FFULL;
    v = (v | (v << 4))  & 0x0F0F0F0F0F0F0F0FULL;
    v = (v | (v << 2))  & 0x3333333333333333ULL;
    v = (v | (v << 1))  & 0x5555555555555555ULL;
    return v;
}

__global__ void __launch_bounds__(128) mask_scan_kernel(const float* __restrict__ thrp,
                                                        const float* __restrict__ scores,
                                                        float* __restrict__ out) {
    const int by = blockIdx.y, bx = blockIdx.x;
    if (bx < by) return;                  // lower-triangle words never written (stay 0)
    const int t = threadIdx.x;

    __shared__ __align__(16) union {
        struct { float sA[1024]; float sB[1024]; u16 queue[4096]; } m;   // 16.5KB
        u64 sdiag[NB];                                                   // 16KB (scan tail)
    } shm;
    __shared__ u64 sbits[64];
    __shared__ int qcnt;
    __shared__ int is_last;
    __shared__ u64 snz[NWORDS], s_keep[NWORDS];

    for (int q = t; q < 1024; q += 128) {
        shm.m.sB[q] = g_pboxs[bx * 1024 + q];
        shm.m.sA[q] = g_pboxs[by * 1024 + q];
    }
    if (t < 64) sbits[t] = 0ULL;
    if (t == 0) qcnt = 0;
    __syncthreads();

    // circle filter: 2 threads per row, 32 columns each
    {
        const int row  = t & 63;
        const int half = t >> 6;
        const float acx = shm.m.sA[row * 16 + 8];
        const float acy = shm.m.sA[row * 16 + 9];
        const float ard = shm.m.sA[row * 16 + 15];
        const int jlo = (bx == by) ? row + 1 : 0;
        const int j0 = half * 32, j1 = j0 + 32;
        for (int j = j0; j < j1; j++) {
            if (j < jlo) continue;
            float dx = acx - shm.m.sB[j * 16 + 8], dy = acy - shm.m.sB[j * 16 + 9];
            float rr = ard + shm.m.sB[j * 16 + 15];
            if (dx * dx + dy * dy <= rr * rr) {          // circle overlap -> candidate
                int q = atomicAdd(&qcnt, 1);
                shm.m.queue[q] = (u16)((row << 6) | j);
            }
        }
    }
    __syncthreads();

    const int n = qcnt;
    const float thr = thrp[0];
    for (int q = t; q < n; q += 128) {
        u16 v = shm.m.queue[q];
        int ti = v >> 6, j = v & 63;

        float A[16], B[16];
        const float4* Ap = (const float4*)&shm.m.sA[ti * 16];
        const float4* Bp = (const float4*)&shm.m.sB[j * 16];
#pragma unroll
        for (int r = 0; r < 4; r++) {
            float4 va = Ap[r], vb = Bp[r];
            A[r*4+0]=va.x; A[r*4+1]=va.y; A[r*4+2]=va.z; A[r*4+3]=va.w;
            B[r*4+0]=vb.x; B[r*4+1]=vb.y; B[r*4+2]=vb.z; B[r*4+3]=vb.w;
        }
        float inter = pair_inter_area(A, B);
        float iou = xdiv(inter, xadd(xsub(xadd(A[14], B[14]), inter), 1e-9f));
        if (iou > thr) atomicOr(&sbits[ti], 1ULL << j);
    }
    __syncthreads();

    if (t < 64) {
        u64 w = sbits[t];
        g_mask[(by * 64 + t) * NWORDS + bx] = w;   // block exclusively owns these words
        if (bx == by) g_diag[by * 64 + t] = w;
        if (w) atomicOr(&g_rownz[by], 1ULL << t);
    }

    // ---- completion: last of the 528 participating blocks runs the scan ----
    __threadfence();
    if (t == 0) {
        int d = atomicAdd(&g_done, 1);
        is_last = (d == NTILES - 1);
    }
    __syncthreads();
    if (!is_last) return;
    __threadfence();
    __syncthreads();   // smem union reuse barrier

    // ---- scan tail (one block, 128 threads) ----
    for (int i = t; i < NB; i += 128) shm.sdiag[i] = g_diag[i];   // coalesced 16KB
    if (t < NWORDS) snz[t] = g_rownz[t];
    __syncthreads();

    if (t < 32) {
        const int lane = t;
        u64 rem = 0ULL;   // lane's suppression word
        for (int c = 0; c < NWORDS; c++) {
            u64 cur = __shfl_sync(0xFFFFFFFFu, rem, c);

            u64 w0 = shm.sdiag[c * 64 + lane * 2];
            u64 w1 = shm.sdiag[c * 64 + lane * 2 + 1];
            u32 b0 = __ballot_sync(0xFFFFFFFFu, w0 != 0ULL);
            u32 b1 = __ballot_sync(0xFFFFFFFFu, w1 != 0ULL);
            u64 nzd = morton_even(b0) | (morton_even(b1) << 1);

            // sparse serial resolve (all lanes redundantly; smem broadcast)
            u64 A = 0ULL, covered = 0ULL;
            u64 m = nzd;
            while (m) {
                int pbit = __ffsll((long long)m) - 1; m &= m - 1;
                u64 range = ((2ULL << pbit) - 1ULL) & ~covered;
                A |= (~cur) & range;
                covered |= range;
                if ((A >> pbit) & 1ULL) cur |= shm.sdiag[c * 64 + pbit];
            }
            A |= (~cur) & ~covered;

            // OR full rows of alive suppressors: coalesced 256B L2 loads
            u64 need = A & snz[c];
            while (need) {
                int j = __ffsll((long long)need) - 1; need &= need - 1;
                rem |= g_mask[(u32)(c * 64 + j) * NWORDS + lane];
            }
            if (lane == 0) s_keep[c] = A;
        }
    }
    __syncthreads();

    for (int i = t; i < NB; i += 128) {
        int keep = (int)((s_keep[i >> 6] >> (i & 63)) & 1ULL);
        int orig = g_order[i];
        out[orig] = keep ? scores[orig] : 0.0f;
    }
}

// ---------------- launch ----------------
extern "C" void kernel_launch(void* const* d_in, const int* in_sizes, int n_in,
                              void* d_out, int out_size) {
    (void)in_sizes; (void)n_in; (void)out_size;
    const float* boxes  = (const float*)d_in[0];
    const float* scores = (const float*)d_in[1];
    const int*   labels = (const int*)d_in[2];
    const float* thr    = (const float*)d_in[3];
    float* out = (float*)d_out;

    prep_kernel<<<(NB * 32) / 256, 256>>>(boxes, scores, labels);
    mask_scan_kernel<<<dim3(NWORDS, NWORDS), 128>>>(thr, scores, out);
}

// round 6
// speedup vs baseline: 6.2043x; 1.1951x over previous
#include <cuda_runtime.h>
#include <cstdint>

#define NB 2048
#define NWORDS (NB / 64)                     // 32
#define NTILES (NWORDS * (NWORDS + 1) / 2)   // 528 upper-tri blocks
#define CAP_ROWS 640                         // suppressor-row smem cache capacity
#define SCAN_DYN_BYTES (CAP_ROWS * NWORDS * 8)   // 160KB

typedef unsigned long long u64;
typedef unsigned int u32;
typedef unsigned short u16;

// ---------------- device scratch ----------------
__device__ int   g_order[NB];              // sorted pos -> original index
__device__ __align__(16) float g_pboxs[NB * 16];  // SORTED: x0..3,y0..3,cx,cy,c,s,we,he,area,rad
__device__ u64   g_mask[NB * NWORDS];      // suppression bitmask; lower-tri never written, stays 0
__device__ u64   g_diag[NB];               // each row's diagonal-block word (contiguous copy)
__device__ u64   g_rownz[NWORDS];          // bit j of word c -> row c*64+j has any suppression

// exact (non-contracted) fp32 helpers — replicate jax/XLA unfused fp32 ops
__device__ __forceinline__ float xmul(float a, float b) { return __fmul_rn(a, b); }
__device__ __forceinline__ float xadd(float a, float b) { return __fadd_rn(a, b); }
__device__ __forceinline__ float xsub(float a, float b) { return __fsub_rn(a, b); }
__device__ __forceinline__ float xdiv(float a, float b) { return __fdiv_rn(a, b); }
__device__ __forceinline__ float xcross(float ax, float ay, float bx, float by) {
    return xsub(xmul(ax, by), xmul(ay, bx));
}

// ---------------- kernel 1: fused reduce + keys + rank + precompute ----------------
// 256 blocks x 256 threads; one warp per box.
__global__ void __launch_bounds__(256) prep_kernel(const float* __restrict__ boxes,
                                                   const float* __restrict__ scores,
                                                   const int*   __restrict__ labels) {
    __shared__ u32  skeys[NB];
    __shared__ float red[256];
    const int tid = threadIdx.x;

    // m1 tracks max (w*w+h*h); sqrt is correctly rounded (monotone), so
    // max_i sqrt(x_i) == sqrt(max_i x_i) bit-exactly.
    float m1 = -1e30f, m2 = -1e30f;
    for (int q = tid; q < NB; q += 256) {
        float cx = boxes[q * 5 + 0], cy = boxes[q * 5 + 1];
        float w  = boxes[q * 5 + 2], h  = boxes[q * 5 + 3];
        float s2 = xadd(xmul(w, w), xmul(h, h));
        m1 = fmaxf(m1, s2);
        m2 = fmaxf(m2, fmaxf(cx, cy));
        skeys[q] = __float_as_uint(scores[q]) ^ 0xFFFFFFFFu;   // ascending == descending score
    }
    red[tid] = m1; __syncthreads();
    for (int s = 128; s > 0; s >>= 1) { if (tid < s) red[tid] = fmaxf(red[tid], red[tid + s]); __syncthreads(); }
    float maxs = __fsqrt_rn(red[0]); __syncthreads();
    red[tid] = m2; __syncthreads();
    for (int s = 128; s > 0; s >>= 1) { if (tid < s) red[tid] = fmaxf(red[tid], red[tid + s]); __syncthreads(); }
    float maxc = red[0];

    // scale = (max_coord + max_radius)*2 + 1  (exact ref fp32 sequence)
    float scale = xadd(xmul(xadd(maxc, xmul(maxs, 0.5f)), 2.0f), 1.0f);

    if (blockIdx.x == 0 && tid < NWORDS) g_rownz[tid] = 0ULL;

    const int gt   = blockIdx.x * 256 + tid;   // 65536 threads
    const int i    = gt >> 5;                  // original box index
    const int lane = gt & 31;
    const u32 mykey = skeys[i];

    int rank = 0;
    const int q0 = lane * (NB / 32);
#pragma unroll 16
    for (int q = 0; q < NB / 32; q++) {
        u32 kq = skeys[q0 + q];
        rank += (kq < mykey) || (kq == mykey && (q0 + q) < i);   // stable tiebreak
    }
#pragma unroll
    for (int off = 16; off > 0; off >>= 1) rank += __shfl_xor_sync(0xFFFFFFFFu, rank, off);
    if (lane != 0) return;

    float off = xmul((float)labels[i], scale);
    float cx = xadd(boxes[i * 5 + 0], off);
    float cy = xadd(boxes[i * 5 + 1], off);
    float w  = boxes[i * 5 + 2];
    float h  = boxes[i * 5 + 3];
    float a  = boxes[i * 5 + 4];
    float c  = (float)cos((double)a);        // correctly-rounded fp32 trig
    float s  = (float)sin((double)a);
    float wh = xmul(w, 0.5f);
    float hh = xmul(h, 0.5f);

    float* P = &g_pboxs[rank * 16];
#pragma unroll
    for (int q = 0; q < 4; q++) {
        float dx = (q == 1 || q == 2) ? wh : -wh;
        float dy = (q >= 2) ? hh : -hh;
        P[q]     = xsub(xadd(cx, xmul(c, dx)), xmul(s, dy));
        P[4 + q] = xadd(xadd(cy, xmul(s, dx)), xmul(c, dy));
    }
    P[8]  = cx;  P[9]  = cy;  P[10] = c;  P[11] = s;
    P[12] = xadd(wh, 1e-5f);
    P[13] = xadd(hh, 1e-5f);
    P[14] = xmul(w, h);
    P[15] = 0.5f * __fsqrt_rn(w * w + h * h) + 1e-2f;   // conservative circle radius
    g_order[rank] = i;
}

// ---------------- exact-replica pairwise intersection area (compacted) ----------------
__device__ __forceinline__ bool pib(float x, float y, const float* __restrict__ B) {
    float px = xsub(x, B[8]);
    float py = xsub(y, B[9]);
    float lx = xadd(xmul(B[10], px), xmul(B[11], py));     //  c*px + s*py
    float ly = xadd(xmul(-B[11], px), xmul(B[10], py));    // -s*px + c*py
    return (fabsf(lx) <= B[12]) && (fabsf(ly) <= B[13]);
}

__device__ float pair_inter_area(const float* __restrict__ A, const float* __restrict__ B) {
    float px[24], py[24];
    int k = 0;
    float sxm = 0.0f, sym = 0.0f;

    // candidate points appended in reference index order 0..23 -> identical fp sum order
#pragma unroll
    for (int q = 0; q < 4; q++) {
        if (pib(A[q], A[4 + q], B)) {
            px[k] = A[q]; py[k] = A[4 + q];
            sxm = xadd(sxm, A[q]); sym = xadd(sym, A[4 + q]); k++;
        }
    }
#pragma unroll
    for (int q = 0; q < 4; q++) {
        if (pib(B[q], B[4 + q], A)) {
            px[k] = B[q]; py[k] = B[4 + q];
            sxm = xadd(sxm, B[q]); sym = xadd(sym, B[4 + q]); k++;
        }
    }
#pragma unroll
    for (int ea = 0; ea < 4; ea++) {
        float pxx = A[ea], pyy = A[4 + ea];
        float rx = xsub(A[(ea + 1) & 3], pxx), ry = xsub(A[4 + ((ea + 1) & 3)], pyy);
#pragma unroll
        for (int eb = 0; eb < 4; eb++) {
            float qx = B[eb], qy = B[4 + eb];
            float sx = xsub(B[(eb + 1) & 3], qx), sy = xsub(B[4 + ((eb + 1) & 3)], qy);
            float den = xcross(rx, ry, sx, sy);
            float qpx = xsub(qx, pxx), qpy = xsub(qy, pyy);
            if (fabsf(den) > 1e-9f) {
                float tt = xdiv(xcross(qpx, qpy, sx, sy), den);
                float uu = xdiv(xcross(qpx, qpy, rx, ry), den);
                if (tt >= 0.0f && tt <= 1.0f && uu >= 0.0f && uu <= 1.0f) {
                    float ix = xadd(pxx, xmul(tt, rx));
                    float iy = xadd(pyy, xmul(tt, ry));
                    px[k] = ix; py[k] = iy;
                    sxm = xadd(sxm, ix); sym = xadd(sym, iy); k++;
                }
            }
        }
    }
    if (k < 3) return 0.0f;

    float kk  = (float)k;
    float cxm = xdiv(sxm, kk), cym = xdiv(sym, kk);

    float dxr[24], dyr[24];
    u64 key[24];
    for (int q = 0; q < k; q++) {
        float dx = xsub(px[q], cxm);
        float dy = xsub(py[q], cym);
        dxr[q] = dx; dyr[q] = dy;
        float a = atan2f(dy, dx);
        u32 b = __float_as_uint(a);
        b = (b & 0x80000000u) ? ~b : (b | 0x80000000u);   // monotone map
        key[q] = ((u64)b << 5) | (u32)q;                   // unique -> stable order
    }
    for (int q = 1; q < k; q++) {          // insertion sort, k typically 4-8
        u64 kq = key[q]; int r = q - 1;
        while (r >= 0 && key[r] > kq) { key[r + 1] = key[r]; r--; }
        key[r + 1] = kq;
    }

    float tot = 0.0f;
    for (int q = 0; q < k; q++) {
        int nq = (q + 1 < k) ? q + 1 : 0;
        int a0 = (int)(key[q]  & 31u);
        int a1 = (int)(key[nq] & 31u);
        tot = xadd(tot, xcross(dxr[a0], dyr[a0], dxr[a1], dyr[a1]));
    }
    return xmul(0.5f, fabsf(tot));
}

// ---------------- kernel 2: fused circle-filter + IoU per 64x64 tile ----------------
__global__ void __launch_bounds__(128) mask_kernel(const float* __restrict__ thrp) {
    // linear blockIdx -> upper-tri (by, bx)
    int b = blockIdx.x;
    int by = 0;
    while (b >= NWORDS - by) { b -= NWORDS - by; by++; }
    const int bx = by + b;
    const int t = threadIdx.x;

    __shared__ __align__(16) float sA[1024];
    __shared__ __align__(16) float sB[1024];
    __shared__ u64 sbits[64];
    __shared__ u16 queue[4096];
    __shared__ int qcnt;

    {   // float4 tile loads (2 iters per array per thread)
        const float4* srcB = (const float4*)&g_pboxs[bx * 1024];
        const float4* srcA = (const float4*)&g_pboxs[by * 1024];
        float4* dB = (float4*)sB;
        float4* dA = (float4*)sA;
        for (int q = t; q < 256; q += 128) { dB[q] = srcB[q]; dA[q] = srcA[q]; }
    }
    if (t < 64) sbits[t] = 0ULL;
    if (t == 0) qcnt = 0;
    __syncthreads();

    // circle filter: 2 threads per row, 32 columns each
    {
        const int row  = t & 63;
        const int half = t >> 6;
        const float acx = sA[row * 16 + 8];
        const float acy = sA[row * 16 + 9];
        const float ard = sA[row * 16 + 15];
        const int jlo = (bx == by) ? row + 1 : 0;
        const int j0 = half * 32, j1 = j0 + 32;
        for (int j = j0; j < j1; j++) {
            if (j < jlo) continue;
            float dx = acx - sB[j * 16 + 8], dy = acy - sB[j * 16 + 9];
            float rr = ard + sB[j * 16 + 15];
            if (dx * dx + dy * dy <= rr * rr) {          // circle overlap -> candidate
                int q = atomicAdd(&qcnt, 1);
                queue[q] = (u16)((row << 6) | j);
            }
        }
    }
    __syncthreads();

    const int n = qcnt;
    const float thr = thrp[0];
    for (int q = t; q < n; q += 128) {
        u16 v = queue[q];
        int ti = v >> 6, j = v & 63;

        float A[16], B[16];
        const float4* Ap = (const float4*)&sA[ti * 16];
        const float4* Bp = (const float4*)&sB[j * 16];
#pragma unroll
        for (int r = 0; r < 4; r++) {
            float4 va = Ap[r], vb = Bp[r];
            A[r*4+0]=va.x; A[r*4+1]=va.y; A[r*4+2]=va.z; A[r*4+3]=va.w;
            B[r*4+0]=vb.x; B[r*4+1]=vb.y; B[r*4+2]=vb.z; B[r*4+3]=vb.w;
        }
        float inter = pair_inter_area(A, B);
        float iou = xdiv(inter, xadd(xsub(xadd(A[14], B[14]), inter), 1e-9f));
        if (iou > thr) atomicOr(&sbits[ti], 1ULL << j);
    }
    __syncthreads();

    if (t < 64) {
        u64 w = sbits[t];
        g_mask[(by * 64 + t) * NWORDS + bx] = w;   // block exclusively owns these words
        if (bx == by) g_diag[by * 64 + t] = w;
        if (w) atomicOr(&g_rownz[by], 1ULL << t);
    }
}

// ---------------- kernel 3: greedy scan with smem row-cache ----------------
__device__ __forceinline__ u64 morton_even(u32 x) {
    u64 v = x;
    v = (v | (v << 16)) & 0x0000FFFF0000FFFFULL;
    v = (v | (v << 8))  & 0x00FF00FF00FF00FFULL;
    v = (v | (v << 4))  & 0x0F0F0F0F0F0F0F0FULL;
    v = (v | (v << 2))  & 0x3333333333333333ULL;
    v = (v | (v << 1))  & 0x5555555555555555ULL;
    return v;
}

__global__ void __launch_bounds__(256) scan_kernel(const float* __restrict__ scores,
                                                   float* __restrict__ out) {
    extern __shared__ u64 rowsbuf[];     // CAP_ROWS x NWORDS words (dynamic, 160KB)
    __shared__ u64 sdiag[NB];            // 16KB
    __shared__ u64 snz[NWORDS], s_keep[NWORDS];
    __shared__ int cbase[NWORDS + 1];
    __shared__ int rowid[CAP_ROWS];
    const int t = threadIdx.x;

    for (int i = t; i < NB; i += 256) sdiag[i] = g_diag[i];   // coalesced 16KB
    if (t < NWORDS) snz[t] = g_rownz[t];
    __syncthreads();

    if (t == 0) {
        int acc = 0;
        for (int c = 0; c < NWORDS; c++) { cbase[c] = acc; acc += __popcll(snz[c]); }
        cbase[NWORDS] = acc;
    }
    __syncthreads();
    const int R = cbase[NWORDS];

    // slot -> global row map (parallel over chunks)
    if (t < NWORDS) {
        int slot = cbase[t];
        u64 m = snz[t];
        while (m) {
            int j = __ffsll((long long)m) - 1; m &= m - 1;
            if (slot < CAP_ROWS) rowid[slot] = t * 64 + j;
            slot++;
        }
    }
    __syncthreads();

    // copy suppressor rows into smem cache (coalesced 256B per row)
    const int Rc = (R < CAP_ROWS) ? R : CAP_ROWS;
    for (int w = t; w < Rc * NWORDS; w += 256)
        rowsbuf[w] = g_mask[(u32)rowid[w >> 5] * NWORDS + (w & 31)];
    __syncthreads();

    if (t < 32) {
        const int lane = t;
        u64 rem = 0ULL;   // lane's suppression word
        for (int c = 0; c < NWORDS; c++) {
            u64 cur = __shfl_sync(0xFFFFFFFFu, rem, c);

            u64 w0 = sdiag[c * 64 + lane * 2];
            u64 w1 = sdiag[c * 64 + lane * 2 + 1];
            u32 b0 = __ballot_sync(0xFFFFFFFFu, w0 != 0ULL);
            u32 b1 = __ballot_sync(0xFFFFFFFFu, w1 != 0ULL);
            u64 nzd = morton_even(b0) | (morton_even(b1) << 1);

            // sparse serial resolve (all lanes redundantly; smem broadcast)
            u64 A = 0ULL, covered = 0ULL;
            u64 m = nzd;
            while (m) {
                int pbit = __ffsll((long long)m) - 1; m &= m - 1;
                u64 range = ((2ULL << pbit) - 1ULL) & ~covered;
                A |= (~cur) & range;
                covered |= range;
                if ((A >> pbit) & 1ULL) cur |= sdiag[c * 64 + pbit];
            }
            A |= (~cur) & ~covered;

            // OR full rows of alive suppressors from the smem cache
            u64 need = A & snz[c];
            const u64 sc = snz[c];
            const int base = cbase[c];
            while (need) {
                int j = __ffsll((long long)need) - 1; need &= need - 1;
                int slot = base + (int)__popcll(sc & ((1ULL << j) - 1ULL));
                u64 v = (slot < CAP_ROWS) ? rowsbuf[slot * NWORDS + lane]
                                          : g_mask[(u32)(c * 64 + j) * NWORDS + lane];
                rem |= v;
            }
            if (lane == 0) s_keep[c] = A;
        }
    }
    __syncthreads();

    for (int i = t; i < NB; i += 256) {
        int keep = (int)((s_keep[i >> 6] >> (i & 63)) & 1ULL);
        int orig = g_order[i];
        out[orig] = keep ? scores[orig] : 0.0f;
    }
}

// ---------------- launch ----------------
extern "C" void kernel_launch(void* const* d_in, const int* in_sizes, int n_in,
                              void* d_out, int out_size) {
    (void)in_sizes; (void)n_in; (void)out_size;
    const float* boxes  = (const float*)d_in[0];
    const float* scores = (const float*)d_in[1];
    const int*   labels = (const int*)d_in[2];
    const float* thr    = (const float*)d_in[3];
    float* out = (float*)d_out;

    cudaFuncSetAttribute(scan_kernel, cudaFuncAttributeMaxDynamicSharedMemorySize,
                         SCAN_DYN_BYTES);

    prep_kernel<<<(NB * 32) / 256, 256>>>(boxes, scores, labels);
    mask_kernel<<<NTILES, 128>>>(thr);
    scan_kernel<<<1, 256, SCAN_DYN_BYTES>>>(scores, out);
}

// round 7
// speedup vs baseline: 6.9751x; 1.1243x over previous
#include <cuda_runtime.h>
#include <cstdint>

#define NB 2048
#define NWORDS (NB / 64)                     // 32
#define NTILES (NWORDS * (NWORDS + 1) / 2)   // 528 upper-tri blocks
#define CAP_ROWS 640                         // suppressor-row smem cache capacity
#define SCAN_DYN_BYTES (CAP_ROWS * NWORDS * 8)   // 160KB

typedef unsigned long long u64;
typedef unsigned int u32;
typedef unsigned short u16;

// ---------------- device scratch ----------------
__device__ int   g_order[NB];              // sorted pos -> original index
__device__ __align__(16) float g_pboxs[NB * 16];  // SORTED: x0..3,y0..3,cx,cy,c,s,we,he,area,rad
__device__ u64   g_mask[NB * NWORDS];      // suppression bitmask; lower-tri never written, stays 0
__device__ u64   g_diag[NB];               // each row's diagonal-block word (contiguous copy)
__device__ u64   g_rownz[NWORDS];          // bit j of word c -> row c*64+j has any suppression

// exact (non-contracted) fp32 helpers — replicate jax/XLA unfused fp32 ops
__device__ __forceinline__ float xmul(float a, float b) { return __fmul_rn(a, b); }
__device__ __forceinline__ float xadd(float a, float b) { return __fadd_rn(a, b); }
__device__ __forceinline__ float xsub(float a, float b) { return __fsub_rn(a, b); }
__device__ __forceinline__ float xdiv(float a, float b) { return __fdiv_rn(a, b); }
__device__ __forceinline__ float xcross(float ax, float ay, float bx, float by) {
    return xsub(xmul(ax, by), xmul(ay, bx));
}

// ---------------- kernel 1: fused reduce + keys + rank + precompute ----------------
// 256 blocks x 256 threads; one warp per box.
__global__ void __launch_bounds__(256) prep_kernel(const float* __restrict__ boxes,
                                                   const float* __restrict__ scores,
                                                   const int*   __restrict__ labels) {
    __shared__ u32  skeys[NB];
    __shared__ float red[256];
    const int tid = threadIdx.x;

    // m1 tracks max (w*w+h*h); sqrt is correctly rounded (monotone), so
    // max_i sqrt(x_i) == sqrt(max_i x_i) bit-exactly.
    float m1 = -1e30f, m2 = -1e30f;
    for (int q = tid; q < NB; q += 256) {
        float cx = boxes[q * 5 + 0], cy = boxes[q * 5 + 1];
        float w  = boxes[q * 5 + 2], h  = boxes[q * 5 + 3];
        float s2 = xadd(xmul(w, w), xmul(h, h));
        m1 = fmaxf(m1, s2);
        m2 = fmaxf(m2, fmaxf(cx, cy));
        skeys[q] = __float_as_uint(scores[q]) ^ 0xFFFFFFFFu;   // ascending == descending score
    }
    red[tid] = m1; __syncthreads();
    for (int s = 128; s > 0; s >>= 1) { if (tid < s) red[tid] = fmaxf(red[tid], red[tid + s]); __syncthreads(); }
    float maxs = __fsqrt_rn(red[0]); __syncthreads();
    red[tid] = m2; __syncthreads();
    for (int s = 128; s > 0; s >>= 1) { if (tid < s) red[tid] = fmaxf(red[tid], red[tid + s]); __syncthreads(); }
    float maxc = red[0];

    // scale = (max_coord + max_radius)*2 + 1  (exact ref fp32 sequence)
    float scale = xadd(xmul(xadd(maxc, xmul(maxs, 0.5f)), 2.0f), 1.0f);

    if (blockIdx.x == 0 && tid < NWORDS) g_rownz[tid] = 0ULL;

    const int gt   = blockIdx.x * 256 + tid;   // 65536 threads
    const int i    = gt >> 5;                  // original box index
    const int lane = gt & 31;
    const u32 mykey = skeys[i];

    // interleaved partition: lane reads skeys[lane + 32*q] -> bank == lane,
    // conflict-free LDS (rank is a commutative sum, partition order irrelevant)
    int rank = 0;
#pragma unroll 16
    for (int q = lane; q < NB; q += 32) {
        u32 kq = skeys[q];
        rank += (kq < mykey) || (kq == mykey && q < i);   // stable tiebreak
    }
#pragma unroll
    for (int off = 16; off > 0; off >>= 1) rank += __shfl_xor_sync(0xFFFFFFFFu, rank, off);
    if (lane != 0) return;

    float off = xmul((float)labels[i], scale);
    float cx = xadd(boxes[i * 5 + 0], off);
    float cy = xadd(boxes[i * 5 + 1], off);
    float w  = boxes[i * 5 + 2];
    float h  = boxes[i * 5 + 3];
    float a  = boxes[i * 5 + 4];
    float c  = (float)cos((double)a);        // correctly-rounded fp32 trig
    float s  = (float)sin((double)a);
    float wh = xmul(w, 0.5f);
    float hh = xmul(h, 0.5f);

    float* P = &g_pboxs[rank * 16];
#pragma unroll
    for (int q = 0; q < 4; q++) {
        float dx = (q == 1 || q == 2) ? wh : -wh;
        float dy = (q >= 2) ? hh : -hh;
        P[q]     = xsub(xadd(cx, xmul(c, dx)), xmul(s, dy));
        P[4 + q] = xadd(xadd(cy, xmul(s, dx)), xmul(c, dy));
    }
    P[8]  = cx;  P[9]  = cy;  P[10] = c;  P[11] = s;
    P[12] = xadd(wh, 1e-5f);
    P[13] = xadd(hh, 1e-5f);
    P[14] = xmul(w, h);
    P[15] = 0.5f * __fsqrt_rn(w * w + h * h) + 1e-2f;   // conservative circle radius
    g_order[rank] = i;
}

// ---------------- exact-replica pairwise intersection area (compacted) ----------------
__device__ __forceinline__ bool pib(float x, float y, const float* __restrict__ B) {
    float px = xsub(x, B[8]);
    float py = xsub(y, B[9]);
    float lx = xadd(xmul(B[10], px), xmul(B[11], py));     //  c*px + s*py
    float ly = xadd(xmul(-B[11], px), xmul(B[10], py));    // -s*px + c*py
    return (fabsf(lx) <= B[12]) && (fabsf(ly) <= B[13]);
}

__device__ float pair_inter_area(const float* __restrict__ A, const float* __restrict__ B) {
    float px[24], py[24];
    int k = 0;
    float sxm = 0.0f, sym = 0.0f;

    // candidate points appended in reference index order 0..23 -> identical fp sum order
#pragma unroll
    for (int q = 0; q < 4; q++) {
        if (pib(A[q], A[4 + q], B)) {
            px[k] = A[q]; py[k] = A[4 + q];
            sxm = xadd(sxm, A[q]); sym = xadd(sym, A[4 + q]); k++;
        }
    }
#pragma unroll
    for (int q = 0; q < 4; q++) {
        if (pib(B[q], B[4 + q], A)) {
            px[k] = B[q]; py[k] = B[4 + q];
            sxm = xadd(sxm, B[q]); sym = xadd(sym, B[4 + q]); k++;
        }
    }
#pragma unroll
    for (int ea = 0; ea < 4; ea++) {
        float pxx = A[ea], pyy = A[4 + ea];
        float rx = xsub(A[(ea + 1) & 3], pxx), ry = xsub(A[4 + ((ea + 1) & 3)], pyy);
#pragma unroll
        for (int eb = 0; eb < 4; eb++) {
            float qx = B[eb], qy = B[4 + eb];
            float sx = xsub(B[(eb + 1) & 3], qx), sy = xsub(B[4 + ((eb + 1) & 3)], qy);
            float den = xcross(rx, ry, sx, sy);
            float qpx = xsub(qx, pxx), qpy = xsub(qy, pyy);
            if (fabsf(den) > 1e-9f) {
                float tt = xdiv(xcross(qpx, qpy, sx, sy), den);
                float uu = xdiv(xcross(qpx, qpy, rx, ry), den);
                if (tt >= 0.0f && tt <= 1.0f && uu >= 0.0f && uu <= 1.0f) {
                    float ix = xadd(pxx, xmul(tt, rx));
                    float iy = xadd(pyy, xmul(tt, ry));
                    px[k] = ix; py[k] = iy;
                    sxm = xadd(sxm, ix); sym = xadd(sym, iy); k++;
                }
            }
        }
    }
    if (k < 3) return 0.0f;

    float kk  = (float)k;
    float cxm = xdiv(sxm, kk), cym = xdiv(sym, kk);

    float dxr[24], dyr[24];
    u64 key[24];
    for (int q = 0; q < k; q++) {
        float dx = xsub(px[q], cxm);
        float dy = xsub(py[q], cym);
        dxr[q] = dx; dyr[q] = dy;
        float a = atan2f(dy, dx);
        u32 b = __float_as_uint(a);
        b = (b & 0x80000000u) ? ~b : (b | 0x80000000u);   // monotone map
        key[q] = ((u64)b << 5) | (u32)q;                   // unique -> stable order
    }
    for (int q = 1; q < k; q++) {          // insertion sort, k typically 4-8
        u64 kq = key[q]; int r = q - 1;
        while (r >= 0 && key[r] > kq) { key[r + 1] = key[r]; r--; }
        key[r + 1] = kq;
    }

    float tot = 0.0f;
    for (int q = 0; q < k; q++) {
        int nq = (q + 1 < k) ? q + 1 : 0;
        int a0 = (int)(key[q]  & 31u);
        int a1 = (int)(key[nq] & 31u);
        tot = xadd(tot, xcross(dxr[a0], dyr[a0], dxr[a1], dyr[a1]));
    }
    return xmul(0.5f, fabsf(tot));
}

// ---------------- kernel 2: fused circle-filter + IoU per 64x64 tile ----------------
__global__ void __launch_bounds__(128) mask_kernel(const float* __restrict__ thrp) {
    // linear blockIdx -> upper-tri (by, bx)
    int b = blockIdx.x;
    int by = 0;
    while (b >= NWORDS - by) { b -= NWORDS - by; by++; }
    const int bx = by + b;
    const int t = threadIdx.x;

    __shared__ __align__(16) float sA[1024];
    __shared__ __align__(16) float sB[1024];
    __shared__ u64 sbits[64];
    __shared__ u16 queue[4096];
    __shared__ int qcnt;

    {   // float4 tile loads (2 iters per array per thread)
        const float4* srcB = (const float4*)&g_pboxs[bx * 1024];
        const float4* srcA = (const float4*)&g_pboxs[by * 1024];
        float4* dB = (float4*)sB;
        float4* dA = (float4*)sA;
        for (int q = t; q < 256; q += 128) { dB[q] = srcB[q]; dA[q] = srcA[q]; }
    }
    if (t < 64) sbits[t] = 0ULL;
    if (t == 0) qcnt = 0;
    __syncthreads();

    // circle filter: 2 threads per row, 32 columns each
    {
        const int row  = t & 63;
        const int half = t >> 6;
        const float acx = sA[row * 16 + 8];
        const float acy = sA[row * 16 + 9];
        const float ard = sA[row * 16 + 15];
        const int jlo = (bx == by) ? row + 1 : 0;
        const int j0 = half * 32, j1 = j0 + 32;
        for (int j = j0; j < j1; j++) {
            if (j < jlo) continue;
            float dx = acx - sB[j * 16 + 8], dy = acy - sB[j * 16 + 9];
            float rr = ard + sB[j * 16 + 15];
            if (dx * dx + dy * dy <= rr * rr) {          // circle overlap -> candidate
                int q = atomicAdd(&qcnt, 1);
                queue[q] = (u16)((row << 6) | j);
            }
        }
    }
    __syncthreads();

    const int n = qcnt;
    const float thr = thrp[0];
    for (int q = t; q < n; q += 128) {
        u16 v = queue[q];
        int ti = v >> 6, j = v & 63;

        float A[16], B[16];
        const float4* Ap = (const float4*)&sA[ti * 16];
        const float4* Bp = (const float4*)&sB[j * 16];
#pragma unroll
        for (int r = 0; r < 4; r++) {
            float4 va = Ap[r], vb = Bp[r];
            A[r*4+0]=va.x; A[r*4+1]=va.y; A[r*4+2]=va.z; A[r*4+3]=va.w;
            B[r*4+0]=vb.x; B[r*4+1]=vb.y; B[r*4+2]=vb.z; B[r*4+3]=vb.w;
        }
        float inter = pair_inter_area(A, B);
        float iou = xdiv(inter, xadd(xsub(xadd(A[14], B[14]), inter), 1e-9f));
        if (iou > thr) atomicOr(&sbits[ti], 1ULL << j);
    }
    __syncthreads();

    if (t < 64) {
        u64 w = sbits[t];
        g_mask[(by * 64 + t) * NWORDS + bx] = w;   // block exclusively owns these words
        if (bx == by) g_diag[by * 64 + t] = w;
        if (w) atomicOr(&g_rownz[by], 1ULL << t);
    }
}

// ---------------- kernel 3: greedy scan with smem row-cache ----------------
__device__ __forceinline__ u64 morton_even(u32 x) {
    u64 v = x;
    v = (v | (v << 16)) & 0x0000FFFF0000FFFFULL;
    v = (v | (v << 8))  & 0x00FF00FF00FF00FFULL;
    v = (v | (v << 4))  & 0x0F0F0F0F0F0F0F0FULL;
    v = (v | (v << 2))  & 0x3333333333333333ULL;
    v = (v | (v << 1))  & 0x5555555555555555ULL;
    return v;
}

__global__ void __launch_bounds__(256) scan_kernel(const float* __restrict__ scores,
                                                   float* __restrict__ out) {
    extern __shared__ u64 rowsbuf[];     // CAP_ROWS x NWORDS words (dynamic, 160KB)
    __shared__ u64 sdiag[NB];            // 16KB
    __shared__ u64 snz[NWORDS], s_keep[NWORDS];
    __shared__ int cbase[NWORDS + 1];
    __shared__ int rowid[CAP_ROWS];
    const int t = threadIdx.x;

    for (int i = t; i < NB; i += 256) sdiag[i] = g_diag[i];   // coalesced 16KB
    if (t < NWORDS) snz[t] = g_rownz[t];
    __syncthreads();

    if (t == 0) {
        int acc = 0;
        for (int c = 0; c < NWORDS; c++) { cbase[c] = acc; acc += __popcll(snz[c]); }
        cbase[NWORDS] = acc;
    }
    __syncthreads();
    const int R = cbase[NWORDS];

    // slot -> global row map (parallel over chunks)
    if (t < NWORDS) {
        int slot = cbase[t];
        u64 m = snz[t];
        while (m) {
            int j = __ffsll((long long)m) - 1; m &= m - 1;
            if (slot < CAP_ROWS) rowid[slot] = t * 64 + j;
            slot++;
        }
    }
    __syncthreads();

    // copy suppressor rows into smem cache (coalesced 256B per row)
    const int Rc = (R < CAP_ROWS) ? R : CAP_ROWS;
    for (int w = t; w < Rc * NWORDS; w += 256)
        rowsbuf[w] = g_mask[(u32)rowid[w >> 5] * NWORDS + (w & 31)];
    __syncthreads();

    if (t < 32) {
        const int lane = t;
        u64 rem = 0ULL;   // lane's suppression word
        for (int c = 0; c < NWORDS; c++) {
            u64 cur = __shfl_sync(0xFFFFFFFFu, rem, c);

            u64 w0 = sdiag[c * 64 + lane * 2];
            u64 w1 = sdiag[c * 64 + lane * 2 + 1];
            u32 b0 = __ballot_sync(0xFFFFFFFFu, w0 != 0ULL);
            u32 b1 = __ballot_sync(0xFFFFFFFFu, w1 != 0ULL);
            u64 nzd = morton_even(b0) | (morton_even(b1) << 1);

            // sparse serial resolve (all lanes redundantly; smem broadcast)
            u64 A = 0ULL, covered = 0ULL;
            u64 m = nzd;
            while (m) {
                int pbit = __ffsll((long long)m) - 1; m &= m - 1;
                u64 range = ((2ULL << pbit) - 1ULL) & ~covered;
                A |= (~cur) & range;
                covered |= range;
                if ((A >> pbit) & 1ULL) cur |= sdiag[c * 64 + pbit];
            }
            A |= (~cur) & ~covered;

            // OR full rows of alive suppressors from the smem cache
            u64 need = A & snz[c];
            const u64 sc = snz[c];
            const int base = cbase[c];
            while (need) {
                int j = __ffsll((long long)need) - 1; need &= need - 1;
                int slot = base + (int)__popcll(sc & ((1ULL << j) - 1ULL));
                u64 v = (slot < CAP_ROWS) ? rowsbuf[slot * NWORDS + lane]
                                          : g_mask[(u32)(c * 64 + j) * NWORDS + lane];
                rem |= v;
            }
            if (lane == 0) s_keep[c] = A;
        }
    }
    __syncthreads();

    for (int i = t; i < NB; i += 256) {
        int keep = (int)((s_keep[i >> 6] >> (i & 63)) & 1ULL);
        int orig = g_order[i];
        out[orig] = keep ? scores[orig] : 0.0f;
    }
}

// ---------------- launch ----------------
extern "C" void kernel_launch(void* const* d_in, const int* in_sizes, int n_in,
                              void* d_out, int out_size) {
    (void)in_sizes; (void)n_in; (void)out_size;
    const float* boxes  = (const float*)d_in[0];
    const float* scores = (const float*)d_in[1];
    const int*   labels = (const int*)d_in[2];
    const float* thr    = (const float*)d_in[3];
    float* out = (float*)d_out;

    cudaFuncSetAttribute(scan_kernel, cudaFuncAttributeMaxDynamicSharedMemorySize,
                         SCAN_DYN_BYTES);

    prep_kernel<<<(NB * 32) / 256, 256>>>(boxes, scores, labels);
    mask_kernel<<<NTILES, 128>>>(thr);
    scan_kernel<<<1, 256, SCAN_DYN_BYTES>>>(scores, out);
}